// round 13
// baseline (speedup 1.0000x reference)
#include <cuda_runtime.h>
#include <cstdint>

#define NN   8192
#define DIMK 256
#define FULLM 0xFFFFFFFFu

// XLA EmitTanh f32 clamp constant (validated: rel_err == 0.0)
#define KMAX_TANH 7.99881172180175781f

// Stripe width: per-row top-32 completes within the first few hundred cols;
// 512 = wide margin. Beyond it the cold path recomputes (exact, slow, ~never).
#define STRIPE_TILES 4            // 4 tiles x 128 cols = 512
#define STRIPE_COLS  (STRIPE_TILES * 128)

// Scratch (device globals — no allocation allowed)
__device__ float g_e1t[DIMK * NN];             // emb1^T  [k][node]
__device__ float g_e2t[DIMK * NN];             // emb2^T
__device__ float g_w1t[DIMK * DIMK];           // W1^T    [k][col]
__device__ float g_w2t[DIMK * DIMK];           // W2^T
__device__ float g_nv1t[DIMK * NN];            // nv1^T   [k][node]
__device__ float g_nv2t[DIMK * NN];            // nv2^T
__device__ float g_S[(size_t)NN * NN];         // similarity (stripes only)

// ---------------------------------------------------------------------------
// Eigen/XLA rational tanh (fma Horner), clamped at +/-KMAX_TANH.
// ---------------------------------------------------------------------------
__device__ __forceinline__ float tanh_nv(float x) {
    float t = fminf(fmaxf(x, -KMAX_TANH), KMAX_TANH);
    float x2 = __fmul_rn(t, t);
    float p = fmaf(x2, -2.76076847742355e-16f, 2.00018790482477e-13f);
    p = fmaf(x2, p, -8.60467152213735e-11f);
    p = fmaf(x2, p,  5.12229709037114e-08f);
    p = fmaf(x2, p,  1.48572235717979e-05f);
    p = fmaf(x2, p,  6.37261928875436e-04f);
    p = fmaf(x2, p,  4.89352455891786e-03f);
    p = __fmul_rn(t, p);
    float q = fmaf(x2, 1.19825839466702e-06f, 1.18534705686654e-04f);
    q = fmaf(x2, q, 2.26843463243900e-03f);
    q = fmaf(x2, q, 4.89352518554385e-03f);
    float r = __fdiv_rn(p, q);
    return (fabsf(x) < 0.0004f) ? x : r;
}

// relu(tanh(3a)) with the decision boundary explicit (tie class == 1.0f).
__device__ __forceinline__ float adj_val(float a) {
    float x = __fmul_rn(3.0f, a);
    if (x >= KMAX_TANH) return 1.0f;
    if (x <= 0.0f)      return 0.0f;
    float x2 = __fmul_rn(x, x);
    float p = fmaf(x2, -2.76076847742355e-16f, 2.00018790482477e-13f);
    p = fmaf(x2, p, -8.60467152213735e-11f);
    p = fmaf(x2, p,  5.12229709037114e-08f);
    p = fmaf(x2, p,  1.48572235717979e-05f);
    p = fmaf(x2, p,  6.37261928875436e-04f);
    p = fmaf(x2, p,  4.89352455891786e-03f);
    p = __fmul_rn(x, p);
    float q = fmaf(x2, 1.19825839466702e-06f, 1.18534705686654e-04f);
    q = fmaf(x2, q, 2.26843463243900e-03f);
    q = fmaf(x2, q, 4.89352518554385e-03f);
    float r = __fdiv_rn(p, q);
    return (x < 0.0004f) ? x : r;
}

// Packed f32x2 helpers (each lane rounds exactly like a scalar FFMA)
__device__ __forceinline__ unsigned long long dup2(float x) {
    unsigned long long r;
    asm("mov.b64 %0, {%1, %1};" : "=l"(r) : "f"(x));
    return r;
}
__device__ __forceinline__ void fma2(unsigned long long& d,
                                     unsigned long long a,
                                     unsigned long long b) {
    asm("fma.rn.f32x2 %0, %1, %2, %0;" : "+l"(d) : "l"(a), "l"(b));
}
__device__ __forceinline__ float2 unpk(unsigned long long v) {
    float2 f;
    asm("mov.b64 {%0, %1}, %2;" : "=f"(f.x), "=f"(f.y) : "l"(v));
    return f;
}

__device__ __forceinline__ void cpasync16(uint32_t dst, const float* src) {
    asm volatile("cp.async.cg.shared.global [%0], [%1], 16;" :: "r"(dst), "l"(src));
}

// S element recompute (cold path): identical ascending-k fmaf chain.
__device__ __forceinline__ float s_compute(int r, int c) {
    float acc = 0.0f;
    for (int k = 0; k < DIMK; k++)
        acc = fmaf(g_nv1t[(size_t)k * NN + r], g_nv2t[(size_t)k * NN + c], acc);
    return acc;
}

// ---------------------------------------------------------------------------
// Transpose pre-pass (exact copies): emb1,emb2 -> [k][node]; W1,W2 -> [k][col]
// ---------------------------------------------------------------------------
__global__ __launch_bounds__(256) void transpose_kernel(const float* __restrict__ e1,
                                                        const float* __restrict__ e2,
                                                        const float* __restrict__ w1,
                                                        const float* __restrict__ w2) {
    __shared__ float tile[32][33];
    const int z = blockIdx.z;
    const float* src;
    float* dst;
    int R;                                   // src is [R][DIMK]
    if (z == 0)      { src = e1; dst = g_e1t; R = NN; }
    else if (z == 1) { src = e2; dst = g_e2t; R = NN; }
    else if (z == 2) { src = w1; dst = g_w1t; R = DIMK; }
    else             { src = w2; dst = g_w2t; R = DIMK; }

    const int by = blockIdx.y * 32;
    const int bx = blockIdx.x * 32;
    if (by >= R) return;

    const int tx = threadIdx.x & 31, ty = threadIdx.x >> 5;
#pragma unroll
    for (int i = ty; i < 32; i += 8)
        tile[i][tx] = src[(size_t)(by + i) * DIMK + bx + tx];
    __syncthreads();
#pragma unroll
    for (int i = ty; i < 32; i += 8)
        dst[(size_t)(bx + i) * R + by + tx] = tile[tx][i];
}

// ---------------------------------------------------------------------------
// Shared GEMM shape: 128x128 CTA tile, 128 threads, thread tile 8 rows x 16
// cols (acc = 4 row-pair x 16 col packed f32x2). Per warp per k: 6 LDS.128
// for 64 fma2 -> FMA-bound. cp.async double-buffered over 8 k-chunks of 32.
// Each output element: single-accumulator ascending-k chain (validated).
// ---------------------------------------------------------------------------
#define ABUF 8192   // floats per buffer: A tile 4096 + B tile 4096

// loader: lk = tid>>2 (k-row 0..31), lo = (tid&3)*32 (float offset); each
// thread copies 32 consecutive floats per matrix (8 x cp.async 16B).
#define ISSUE_TILES(APTR, ASTRIDE, BPTR, BSTRIDE, ch)                          \
    do {                                                                       \
        int _buf = (ch) & 1;                                                   \
        const float* _a = &(APTR)[(size_t)((ch) * 32 + lk) * (ASTRIDE) + rowBase + lo]; \
        const float* _b = &(BPTR)[(size_t)((ch) * 32 + lk) * (BSTRIDE) + colBase + lo]; \
        uint32_t _da = smb + (uint32_t)(_buf * ABUF + lk * 128 + lo) * 4u;     \
        uint32_t _db = _da + 4096u * 4u;                                       \
        _Pragma("unroll")                                                      \
        for (int _j = 0; _j < 8; _j++) {                                       \
            cpasync16(_da + _j * 16, _a + _j * 4);                             \
            cpasync16(_db + _j * 16, _b + _j * 4);                             \
        }                                                                      \
        asm volatile("cp.async.commit_group;");                                \
    } while (0)

#define GEMM_MAINLOOP(APTR, ASTRIDE, BPTR, BSTRIDE)                            \
    ISSUE_TILES(APTR, ASTRIDE, BPTR, BSTRIDE, 0);                              \
    for (int ch = 0; ch < 8; ch++) {                                           \
        if (ch < 7) {                                                          \
            ISSUE_TILES(APTR, ASTRIDE, BPTR, BSTRIDE, ch + 1);                 \
            asm volatile("cp.async.wait_group 1;");                            \
        } else {                                                               \
            asm volatile("cp.async.wait_group 0;");                            \
        }                                                                      \
        __syncthreads();                                                       \
        const float* A = sm + (ch & 1) * ABUF;                                 \
        const float* B = A + 4096;                                             \
        _Pragma("unroll")                                                      \
        for (int k = 0; k < 32; k++) {                                         \
            ulonglong2 a01 = *(const ulonglong2*)&A[k * 128 + ty * 8];         \
            ulonglong2 a23 = *(const ulonglong2*)&A[k * 128 + ty * 8 + 4];     \
            float4 bv0 = *(const float4*)&B[k * 128 + tx * 16];                \
            float4 bv1 = *(const float4*)&B[k * 128 + tx * 16 + 4];            \
            float4 bv2 = *(const float4*)&B[k * 128 + tx * 16 + 8];            \
            float4 bv3 = *(const float4*)&B[k * 128 + tx * 16 + 12];           \
            unsigned long long ap[4] = {a01.x, a01.y, a23.x, a23.y};           \
            unsigned long long bd[16] = {                                      \
                dup2(bv0.x), dup2(bv0.y), dup2(bv0.z), dup2(bv0.w),            \
                dup2(bv1.x), dup2(bv1.y), dup2(bv1.z), dup2(bv1.w),            \
                dup2(bv2.x), dup2(bv2.y), dup2(bv2.z), dup2(bv2.w),            \
                dup2(bv3.x), dup2(bv3.y), dup2(bv3.z), dup2(bv3.w)};           \
            _Pragma("unroll")                                                  \
            for (int c = 0; c < 16; c++)                                       \
                _Pragma("unroll")                                              \
                for (int p = 0; p < 4; p++)                                    \
                    fma2(acc[p][c], ap[p], bd[c]);                             \
        }                                                                      \
        __syncthreads();                                                       \
    }

// ---------------------------------------------------------------------------
// nv GEMM: nvT = tanh(3*(emb @ W^T + b))^T from embT/WT.  Also zeroes the
// 256MB output with streaming stores that drain under the FMA mainloop.
// Grid (64 rowTiles, 2 colTiles, 2 sets), 128 threads.
// ---------------------------------------------------------------------------
__global__ __launch_bounds__(128, 2) void nv_gemm_kernel(const float* __restrict__ b1,
                                                         const float* __restrict__ b2,
                                                         float* __restrict__ out) {
    extern __shared__ float sm[];
    const int tid = threadIdx.x;
    const int sel = blockIdx.z;
    const float* At   = sel ? g_e2t : g_e1t;
    const float* Bt   = sel ? g_w2t : g_w1t;
    const float* bias = sel ? b2 : b1;
    float* nvT = sel ? g_nv2t : g_nv1t;

    const int rowBase = blockIdx.x * 128;
    const int colBase = blockIdx.y * 128;
    const int ty = tid & 15;          // row group: 8 rows
    const int tx = tid >> 4;          // col group: 16 cols
    const int lk = tid >> 2;
    const int lo = (tid & 3) * 32;
    const uint32_t smb = (uint32_t)__cvta_generic_to_shared(sm);

    unsigned long long acc[4][16];
#pragma unroll
    for (int p = 0; p < 4; p++)
#pragma unroll
        for (int c = 0; c < 16; c++) acc[p][c] = 0ull;

    // prime chunk 0, then zero a slice of the output while it lands
    ISSUE_TILES(At, NN, Bt, DIMK, 0);
    {
        const float4 z = make_float4(0.f, 0.f, 0.f, 0.f);
        float4* o4 = (float4*)out;
        const size_t total4 = (size_t)NN * NN / 4;
        const size_t gsz = (size_t)gridDim.x * gridDim.y * gridDim.z * 128;
        const size_t gid = ((size_t)((blockIdx.z * gridDim.y + blockIdx.y) * gridDim.x
                                     + blockIdx.x)) * 128 + tid;
        for (size_t i = gid; i < total4; i += gsz)
            __stcs(&o4[i], z);
    }
    for (int ch = 0; ch < 8; ch++) {
        if (ch < 7) {
            ISSUE_TILES(At, NN, Bt, DIMK, ch + 1);
            asm volatile("cp.async.wait_group 1;");
        } else {
            asm volatile("cp.async.wait_group 0;");
        }
        __syncthreads();
        const float* A = sm + (ch & 1) * ABUF;
        const float* B = A + 4096;
#pragma unroll
        for (int k = 0; k < 32; k++) {
            ulonglong2 a01 = *(const ulonglong2*)&A[k * 128 + ty * 8];
            ulonglong2 a23 = *(const ulonglong2*)&A[k * 128 + ty * 8 + 4];
            float4 bv0 = *(const float4*)&B[k * 128 + tx * 16];
            float4 bv1 = *(const float4*)&B[k * 128 + tx * 16 + 4];
            float4 bv2 = *(const float4*)&B[k * 128 + tx * 16 + 8];
            float4 bv3 = *(const float4*)&B[k * 128 + tx * 16 + 12];
            unsigned long long ap[4] = {a01.x, a01.y, a23.x, a23.y};
            unsigned long long bd[16] = {
                dup2(bv0.x), dup2(bv0.y), dup2(bv0.z), dup2(bv0.w),
                dup2(bv1.x), dup2(bv1.y), dup2(bv1.z), dup2(bv1.w),
                dup2(bv2.x), dup2(bv2.y), dup2(bv2.z), dup2(bv2.w),
                dup2(bv3.x), dup2(bv3.y), dup2(bv3.z), dup2(bv3.w)};
#pragma unroll
            for (int c = 0; c < 16; c++)
#pragma unroll
                for (int p = 0; p < 4; p++)
                    fma2(acc[p][c], ap[p], bd[c]);
        }
        __syncthreads();
    }

    // epilogue: y = 3*(acc+b) (unfused add then mul), tanh, store transposed
#pragma unroll
    for (int c = 0; c < 16; c++) {
        const int col = colBase + tx * 16 + c;
        const float b = bias[col];
        float2 v01 = unpk(acc[0][c]), v23 = unpk(acc[1][c]);
        float2 v45 = unpk(acc[2][c]), v67 = unpk(acc[3][c]);
        float4 o0, o1;
        o0.x = tanh_nv(__fmul_rn(3.0f, __fadd_rn(v01.x, b)));
        o0.y = tanh_nv(__fmul_rn(3.0f, __fadd_rn(v01.y, b)));
        o0.z = tanh_nv(__fmul_rn(3.0f, __fadd_rn(v23.x, b)));
        o0.w = tanh_nv(__fmul_rn(3.0f, __fadd_rn(v23.y, b)));
        o1.x = tanh_nv(__fmul_rn(3.0f, __fadd_rn(v45.x, b)));
        o1.y = tanh_nv(__fmul_rn(3.0f, __fadd_rn(v45.y, b)));
        o1.z = tanh_nv(__fmul_rn(3.0f, __fadd_rn(v67.x, b)));
        o1.w = tanh_nv(__fmul_rn(3.0f, __fadd_rn(v67.y, b)));
        size_t base = (size_t)col * NN + rowBase + ty * 8;
        *(float4*)&nvT[base]     = o0;
        *(float4*)&nvT[base + 4] = o1;
    }
}

// ---------------------------------------------------------------------------
// Kernel A: stripe GEMM  S = nv1 @ nv2^T  on the cross
//   { all rows x cols[0:512] }  U  { rows[0:512] x all cols }.   496 CTAs.
// ---------------------------------------------------------------------------
__global__ __launch_bounds__(128, 2) void s_gemm_kernel() {
    extern __shared__ float sm[];
    const int tid = threadIdx.x;

    int bid = blockIdx.x;
    int rT, cT;
    if (bid < 64 * STRIPE_TILES) { rT = bid >> 2; cT = bid & 3; }
    else { int b = bid - 64 * STRIPE_TILES; rT = b / 60; cT = 4 + (b - rT * 60); }
    const int rowBase = rT * 128;
    const int colBase = cT * 128;

    const int ty = tid & 15;
    const int tx = tid >> 4;
    const int lk = tid >> 2;
    const int lo = (tid & 3) * 32;
    const uint32_t smb = (uint32_t)__cvta_generic_to_shared(sm);

    unsigned long long acc[4][16];
#pragma unroll
    for (int p = 0; p < 4; p++)
#pragma unroll
        for (int c = 0; c < 16; c++) acc[p][c] = 0ull;

    GEMM_MAINLOOP(g_nv1t, NN, g_nv2t, NN);

    // epilogue: write S rows (two rows per acc pair), 16B vector stores
#pragma unroll
    for (int p = 0; p < 4; p++) {
        float2 u[16];
#pragma unroll
        for (int c = 0; c < 16; c++) u[c] = unpk(acc[p][c]);
        size_t base = (size_t)(rowBase + ty * 8 + 2 * p) * NN + colBase + tx * 16;
#pragma unroll
        for (int g = 0; g < 4; g++)
            *(float4*)&g_S[base + 4 * g] =
                make_float4(u[4*g].x, u[4*g+1].x, u[4*g+2].x, u[4*g+3].x);
        base += NN;
#pragma unroll
        for (int g = 0; g < 4; g++)
            *(float4*)&g_S[base + 4 * g] =
                make_float4(u[4*g].y, u[4*g+1].y, u[4*g+2].y, u[4*g+3].y);
    }
}

// ---------------------------------------------------------------------------
// Kernel B: ballot-collect the first 32 exact-1.0 columns per row (exact:
// tanh <= 1 and stable top_k prefers lower index). Fallback: generic exact
// streaming top-32 for rows with < 32 saturated entries (probability ~0).
// ---------------------------------------------------------------------------
#define SS_PITCH 132
#define ST_PITCH 68

__device__ void generic_row_topk(int r, float* __restrict__ out) {
    const int lane = threadIdx.x & 31;
    unsigned long long key = 0ull, rmin = 0ull;
    for (int cb = 0; cb < NN; cb += 32) {
        int c = cb + lane;
        float sv, tv;
        if (cb + 32 <= STRIPE_COLS) {
            sv = g_S[(size_t)r * NN + c];
            tv = g_S[(size_t)c * NN + r];
        } else {
            sv = s_compute(r, c);
            tv = s_compute(c, r);
        }
        float v = adj_val(__fsub_rn(sv, tv));
        unsigned long long cand =
            ((unsigned long long)__float_as_uint(v) << 32)
            | (unsigned)(0xFFFFFFFFu - (unsigned)c);
        unsigned m = __ballot_sync(FULLM, cand > rmin);
        while (m) {
            int src = __ffs(m) - 1; m &= m - 1;
            unsigned long long ck = __shfl_sync(FULLM, cand, src);
            if (ck > rmin) {
                unsigned bal = __ballot_sync(FULLM, key == rmin);
                if (lane == (__ffs(bal) - 1)) key = ck;
                unsigned long long mm = key;
#pragma unroll
                for (int o = 16; o > 0; o >>= 1) {
                    unsigned long long om = __shfl_xor_sync(FULLM, mm, o);
                    mm = om < mm ? om : mm;
                }
                rmin = mm;
            }
        }
    }
    unsigned vb = (unsigned)(key >> 32);
    if (vb) {
        unsigned col = 0xFFFFFFFFu - (unsigned)(key & 0xFFFFFFFFull);
        out[(size_t)r * NN + col] = __uint_as_float(vb);
    }
}

__global__ __launch_bounds__(256, 1) void adj_topk2_kernel(float* __restrict__ out) {
    extern __shared__ float sm[];
    float* sS = sm;                            // [64][132]  S[row][col]
    float* sT = sm + 64 * SS_PITCH;            // [128][68]  S[col][row]

    const int rowBase = blockIdx.x * 64;
    const int tid  = threadIdx.x;
    const int lane = tid & 31, wrp = tid >> 5;
    const int sr = tid >> 2, sc = (tid & 3) * 32;
    const int tr = tid >> 1, tcx = (tid & 1) * 32;

    int cnt[8];
    int mycol[8];
#pragma unroll
    for (int q = 0; q < 8; q++) { cnt[q] = 0; mycol[q] = -1; }

    for (int t = 0; t < 64; t++) {
        const int colBase = t * 128;
        if (t < STRIPE_TILES) {
            {
                const float4* src = (const float4*)&g_S[(size_t)(rowBase + sr) * NN + colBase + sc];
                float4* dst = (float4*)&sS[sr * SS_PITCH + sc];
#pragma unroll
                for (int i = 0; i < 8; i++) dst[i] = src[i];
            }
            {
                const float4* src = (const float4*)&g_S[(size_t)(colBase + tr) * NN + rowBase + tcx];
                float4* dst = (float4*)&sT[tr * ST_PITCH + tcx];
#pragma unroll
                for (int i = 0; i < 8; i++) dst[i] = src[i];
            }
        } else {
            for (int e = 0; e < 32; e++)
                sS[sr * SS_PITCH + sc + e] = s_compute(rowBase + sr, colBase + sc + e);
            for (int e = 0; e < 32; e++)
                sT[tr * ST_PITCH + tcx + e] = s_compute(colBase + tr, rowBase + tcx + e);
        }
        __syncthreads();

#pragma unroll
        for (int q = 0; q < 8; q++) {
            if (cnt[q] >= 32) continue;
            const int r = wrp * 8 + q;
#pragma unroll
            for (int s4 = 0; s4 < 4; s4++) {
                const int col = lane + 32 * s4;
                float a = __fsub_rn(sS[r * SS_PITCH + col], sT[col * ST_PITCH + r]);
                float v = adj_val(a);
                unsigned m = __ballot_sync(FULLM, v == 1.0f);
                int avail = __popc(m);
                int nc = min(32 - cnt[q], avail);
                int sl = lane - cnt[q];
                if (sl >= 0 && sl < nc) {
                    int bit = __fns(m, 0, sl + 1);
                    mycol[q] = colBase + 32 * s4 + bit;
                }
                cnt[q] += nc;
                if (cnt[q] >= 32) break;
            }
        }

        bool full = true;
#pragma unroll
        for (int q = 0; q < 8; q++) full &= (cnt[q] >= 32);
        if (__syncthreads_and(full)) break;
    }

#pragma unroll
    for (int q = 0; q < 8; q++) {
        if (cnt[q] >= 32) {
            if (mycol[q] >= 0)
                out[(size_t)(rowBase + wrp * 8 + q) * NN + mycol[q]] = 1.0f;
        } else {
            generic_row_topk(rowBase + wrp * 8 + q, out);
        }
    }
}

// ---------------------------------------------------------------------------
// Inputs (metadata order): idx(int64), scale_idx, scale_set, emb1, emb2,
//                          W1, b1, W2, b2.  Output: float32 [8192*8192].
// ---------------------------------------------------------------------------
extern "C" void kernel_launch(void* const* d_in, const int* in_sizes, int n_in,
                              void* d_out, int out_size) {
    const float* emb1 = (const float*)d_in[3];
    const float* emb2 = (const float*)d_in[4];
    const float* W1   = (const float*)d_in[5];
    const float* b1   = (const float*)d_in[6];
    const float* W2   = (const float*)d_in[7];
    const float* b2   = (const float*)d_in[8];
    float* out = (float*)d_out;

    (void)in_sizes; (void)n_in; (void)out_size;

    static const size_t GEMM_SMEM = 2 * ABUF * sizeof(float);                         // 64KB
    static const size_t ADJ_SMEM  = (64 * SS_PITCH + 128 * ST_PITCH) * sizeof(float); // ~69KB
    cudaFuncSetAttribute(nv_gemm_kernel,
                         cudaFuncAttributeMaxDynamicSharedMemorySize, (int)GEMM_SMEM);
    cudaFuncSetAttribute(s_gemm_kernel,
                         cudaFuncAttributeMaxDynamicSharedMemorySize, (int)GEMM_SMEM);
    cudaFuncSetAttribute(adj_topk2_kernel,
                         cudaFuncAttributeMaxDynamicSharedMemorySize, (int)ADJ_SMEM);

    // 1) exact transposes: embT [k][node], WT [k][col]
    transpose_kernel<<<dim3(DIMK / 32, NN / 32, 4), 256>>>(emb1, emb2, W1, W2);

    // 2) nv GEMM (both sets) + output zeroing under the mainloop
    nv_gemm_kernel<<<dim3(NN / 128, DIMK / 128, 2), 128, GEMM_SMEM>>>(b1, b2, out);

    // 3) stripe GEMM
    s_gemm_kernel<<<64 * STRIPE_TILES + 4 * 60, 128, GEMM_SMEM>>>();

    // 4) top-32 collect + scatter
    adj_topk2_kernel<<<NN / 64, 256, ADJ_SMEM>>>(out);
}

// round 14
// speedup vs baseline: 1.4067x; 1.4067x over previous
#include <cuda_runtime.h>
#include <cstdint>

#define NN   8192
#define DIMK 256
#define FULLM 0xFFFFFFFFu

// XLA EmitTanh f32 clamp constant (validated: rel_err == 0.0)
#define KMAX_TANH 7.99881172180175781f

// Stripe width: per-row saturated count in 256 cols ~ Binom(256,0.41):
// mean 105, sigma 7.9 -> P(<32) ~ 1e-20. Cold path backstops correctness.
#define STRIPE_TILES 2            // 2 tiles x 128 cols = 256
#define STRIPE_COLS  (STRIPE_TILES * 128)

// Scratch (device globals — no allocation allowed)
__device__ float g_e1t[DIMK * NN];             // emb1^T  [k][node]
__device__ float g_e2t[DIMK * NN];             // emb2^T
__device__ float g_w1t[DIMK * DIMK];           // W1^T    [k][col]
__device__ float g_w2t[DIMK * DIMK];           // W2^T
__device__ float g_nv1t[DIMK * NN];            // nv1^T   [k][node]
__device__ float g_nv2t[DIMK * NN];            // nv2^T
__device__ float g_S[(size_t)NN * NN];         // similarity (stripes only)

// ---------------------------------------------------------------------------
// Eigen/XLA rational tanh (fma Horner), clamped at +/-KMAX_TANH.
// ---------------------------------------------------------------------------
__device__ __forceinline__ float tanh_nv(float x) {
    float t = fminf(fmaxf(x, -KMAX_TANH), KMAX_TANH);
    float x2 = __fmul_rn(t, t);
    float p = fmaf(x2, -2.76076847742355e-16f, 2.00018790482477e-13f);
    p = fmaf(x2, p, -8.60467152213735e-11f);
    p = fmaf(x2, p,  5.12229709037114e-08f);
    p = fmaf(x2, p,  1.48572235717979e-05f);
    p = fmaf(x2, p,  6.37261928875436e-04f);
    p = fmaf(x2, p,  4.89352455891786e-03f);
    p = __fmul_rn(t, p);
    float q = fmaf(x2, 1.19825839466702e-06f, 1.18534705686654e-04f);
    q = fmaf(x2, q, 2.26843463243900e-03f);
    q = fmaf(x2, q, 4.89352518554385e-03f);
    float r = __fdiv_rn(p, q);
    return (fabsf(x) < 0.0004f) ? x : r;
}

// relu(tanh(3a)) with the decision boundary explicit (tie class == 1.0f).
__device__ __forceinline__ float adj_val(float a) {
    float x = __fmul_rn(3.0f, a);
    if (x >= KMAX_TANH) return 1.0f;
    if (x <= 0.0f)      return 0.0f;
    float x2 = __fmul_rn(x, x);
    float p = fmaf(x2, -2.76076847742355e-16f, 2.00018790482477e-13f);
    p = fmaf(x2, p, -8.60467152213735e-11f);
    p = fmaf(x2, p,  5.12229709037114e-08f);
    p = fmaf(x2, p,  1.48572235717979e-05f);
    p = fmaf(x2, p,  6.37261928875436e-04f);
    p = fmaf(x2, p,  4.89352455891786e-03f);
    p = __fmul_rn(x, p);
    float q = fmaf(x2, 1.19825839466702e-06f, 1.18534705686654e-04f);
    q = fmaf(x2, q, 2.26843463243900e-03f);
    q = fmaf(x2, q, 4.89352518554385e-03f);
    float r = __fdiv_rn(p, q);
    return (x < 0.0004f) ? x : r;
}

// Packed f32x2 helpers (each lane rounds exactly like a scalar FFMA)
__device__ __forceinline__ unsigned long long dup2(float x) {
    unsigned long long r;
    asm("mov.b64 %0, {%1, %1};" : "=l"(r) : "f"(x));
    return r;
}
__device__ __forceinline__ void fma2(unsigned long long& d,
                                     unsigned long long a,
                                     unsigned long long b) {
    asm("fma.rn.f32x2 %0, %1, %2, %0;" : "+l"(d) : "l"(a), "l"(b));
}
__device__ __forceinline__ float2 unpk(unsigned long long v) {
    float2 f;
    asm("mov.b64 {%0, %1}, %2;" : "=f"(f.x), "=f"(f.y) : "l"(v));
    return f;
}

__device__ __forceinline__ void cpasync16(uint32_t dst, const float* src) {
    asm volatile("cp.async.cg.shared.global [%0], [%1], 16;" :: "r"(dst), "l"(src));
}

// S element recompute (cold path): identical ascending-k fmaf chain.
__device__ __forceinline__ float s_compute(int r, int c) {
    float acc = 0.0f;
    for (int k = 0; k < DIMK; k++)
        acc = fmaf(g_nv1t[(size_t)k * NN + r], g_nv2t[(size_t)k * NN + c], acc);
    return acc;
}

// ---------------------------------------------------------------------------
// Transpose pre-pass (exact copies): emb1,emb2 -> [k][node]; W1,W2 -> [k][col]
// ---------------------------------------------------------------------------
__global__ __launch_bounds__(256) void transpose_kernel(const float* __restrict__ e1,
                                                        const float* __restrict__ e2,
                                                        const float* __restrict__ w1,
                                                        const float* __restrict__ w2) {
    __shared__ float tile[32][33];
    const int z = blockIdx.z;
    const float* src;
    float* dst;
    int R;                                   // src is [R][DIMK]
    if (z == 0)      { src = e1; dst = g_e1t; R = NN; }
    else if (z == 1) { src = e2; dst = g_e2t; R = NN; }
    else if (z == 2) { src = w1; dst = g_w1t; R = DIMK; }
    else             { src = w2; dst = g_w2t; R = DIMK; }

    const int by = blockIdx.y * 32;
    const int bx = blockIdx.x * 32;
    if (by >= R) return;

    const int tx = threadIdx.x & 31, ty = threadIdx.x >> 5;
#pragma unroll
    for (int i = ty; i < 32; i += 8)
        tile[i][tx] = src[(size_t)(by + i) * DIMK + bx + tx];
    __syncthreads();
#pragma unroll
    for (int i = ty; i < 32; i += 8)
        dst[(size_t)(bx + i) * R + by + tx] = tile[tx][i];
}

// ---------------------------------------------------------------------------
// nv GEMM: nvT = tanh(3*(emb @ W^T + b))^T, computed as embT/WT [k][*] GEMM
// with the validated pipeline (fma2 row pairs, cp.async double buffer,
// 256 threads, 8x8 thread tile).  Per-element ascending-k chain.
// ---------------------------------------------------------------------------
#define ABUF 8192   // floats per buffer: A tile 4096 + B tile 4096

#define NV_ISSUE(ch)                                                           \
    do {                                                                       \
        int _buf = (ch) & 1;                                                   \
        const float* _a = &At[(size_t)((ch) * 32 + lk) * NN + rowBase + lo];   \
        const float* _b = &Bt[(size_t)((ch) * 32 + lk) * DIMK + colBase + lo]; \
        uint32_t _da = smb + (uint32_t)(_buf * ABUF + lk * 128 + lo) * 4u;     \
        uint32_t _db = _da + 4096u * 4u;                                       \
        cpasync16(_da,      _a);     cpasync16(_da + 16, _a + 4);              \
        cpasync16(_da + 32, _a + 8); cpasync16(_da + 48, _a + 12);             \
        cpasync16(_db,      _b);     cpasync16(_db + 16, _b + 4);              \
        cpasync16(_db + 32, _b + 8); cpasync16(_db + 48, _b + 12);             \
        asm volatile("cp.async.commit_group;");                                \
    } while (0)

__global__ __launch_bounds__(256, 2) void nv_gemm_kernel(const float* __restrict__ b1,
                                                         const float* __restrict__ b2) {
    extern __shared__ float sm[];
    const int tid = threadIdx.x;
    const int sel = blockIdx.z;
    const float* At   = sel ? g_e2t : g_e1t;
    const float* Bt   = sel ? g_w2t : g_w1t;
    const float* bias = sel ? b2 : b1;
    float* nvT = sel ? g_nv2t : g_nv1t;

    const int rowBase = blockIdx.x * 128;
    const int colBase = blockIdx.y * 128;
    const int ty = tid & 15;
    const int tx = tid >> 4;
    const int lk = tid >> 3;
    const int lo = (tid & 7) * 16;
    const uint32_t smb = (uint32_t)__cvta_generic_to_shared(sm);

    unsigned long long acc[4][8];
#pragma unroll
    for (int p = 0; p < 4; p++)
#pragma unroll
        for (int c = 0; c < 8; c++) acc[p][c] = 0ull;

    NV_ISSUE(0);
    for (int ch = 0; ch < 8; ch++) {
        if (ch < 7) {
            NV_ISSUE(ch + 1);
            asm volatile("cp.async.wait_group 1;");
        } else {
            asm volatile("cp.async.wait_group 0;");
        }
        __syncthreads();

        const float* A = sm + (ch & 1) * ABUF;
        const float* B = A + 4096;
#pragma unroll
        for (int k = 0; k < 32; k++) {
            ulonglong2 a01 = *(const ulonglong2*)&A[k * 128 + ty * 8];
            ulonglong2 a23 = *(const ulonglong2*)&A[k * 128 + ty * 8 + 4];
            float4 bv0 = *(const float4*)&B[k * 128 + tx * 8];
            float4 bv1 = *(const float4*)&B[k * 128 + tx * 8 + 4];
            unsigned long long ap[4] = {a01.x, a01.y, a23.x, a23.y};
            unsigned long long bd[8] = {dup2(bv0.x), dup2(bv0.y), dup2(bv0.z), dup2(bv0.w),
                                        dup2(bv1.x), dup2(bv1.y), dup2(bv1.z), dup2(bv1.w)};
#pragma unroll
            for (int c = 0; c < 8; c++)
#pragma unroll
                for (int p = 0; p < 4; p++)
                    fma2(acc[p][c], ap[p], bd[c]);
        }
        __syncthreads();
    }

    // epilogue: y = 3*(acc+b) (unfused add then mul), tanh, store transposed.
#pragma unroll
    for (int c = 0; c < 8; c++) {
        const int col = colBase + tx * 8 + c;
        const float b = bias[col];
        float2 v01 = unpk(acc[0][c]), v23 = unpk(acc[1][c]);
        float2 v45 = unpk(acc[2][c]), v67 = unpk(acc[3][c]);
        float4 o0, o1;
        o0.x = tanh_nv(__fmul_rn(3.0f, __fadd_rn(v01.x, b)));
        o0.y = tanh_nv(__fmul_rn(3.0f, __fadd_rn(v01.y, b)));
        o0.z = tanh_nv(__fmul_rn(3.0f, __fadd_rn(v23.x, b)));
        o0.w = tanh_nv(__fmul_rn(3.0f, __fadd_rn(v23.y, b)));
        o1.x = tanh_nv(__fmul_rn(3.0f, __fadd_rn(v45.x, b)));
        o1.y = tanh_nv(__fmul_rn(3.0f, __fadd_rn(v45.y, b)));
        o1.z = tanh_nv(__fmul_rn(3.0f, __fadd_rn(v67.x, b)));
        o1.w = tanh_nv(__fmul_rn(3.0f, __fadd_rn(v67.y, b)));
        size_t base = (size_t)col * NN + rowBase + ty * 8;
        *(float4*)&nvT[base]     = o0;
        *(float4*)&nvT[base + 4] = o1;
    }
}

// ---------------------------------------------------------------------------
// Kernel A: stripe GEMM  S = nv1 @ nv2^T  on the cross
//   { all rows x cols[0:256] }  U  { rows[0:256] x all cols }.   252 CTAs.
// Also zeroes the 256MB output (grid-stride streaming stores) UNDER the
// FMA-bound mainloop — replaces a serial memset.
// ---------------------------------------------------------------------------
#define GEMM_ISSUE(ch)                                                         \
    do {                                                                       \
        int _buf = (ch) & 1;                                                   \
        const float* _a = &g_nv1t[(size_t)((ch) * 32 + lk) * NN + rowBase + lo]; \
        const float* _b = &g_nv2t[(size_t)((ch) * 32 + lk) * NN + colBase + lo]; \
        uint32_t _da = smb + (uint32_t)(_buf * ABUF + lk * 128 + lo) * 4u;     \
        uint32_t _db = _da + 4096u * 4u;                                       \
        cpasync16(_da,      _a);     cpasync16(_da + 16, _a + 4);              \
        cpasync16(_da + 32, _a + 8); cpasync16(_da + 48, _a + 12);             \
        cpasync16(_db,      _b);     cpasync16(_db + 16, _b + 4);              \
        cpasync16(_db + 32, _b + 8); cpasync16(_db + 48, _b + 12);             \
        asm volatile("cp.async.commit_group;");                                \
    } while (0)

__global__ __launch_bounds__(256, 2) void s_gemm_kernel(float* __restrict__ out) {
    extern __shared__ float sm[];
    const int tid = threadIdx.x;

    // stripe mapping: first 64*2 CTAs = all 64 row-tiles x col-tiles 0..1;
    // next 2*62 = row-tiles 0..1 x col-tiles 2..63.
    int bid = blockIdx.x;
    int rT, cT;
    if (bid < 64 * STRIPE_TILES) { rT = bid >> 1; cT = bid & 1; }
    else { int b = bid - 64 * STRIPE_TILES; rT = b / 62; cT = 2 + (b - rT * 62); }
    const int rowBase = rT * 128;
    const int colBase = cT * 128;

    const int ty = tid & 15;
    const int tx = tid >> 4;
    const int lk = tid >> 3;
    const int lo = (tid & 7) * 16;
    const uint32_t smb = (uint32_t)__cvta_generic_to_shared(sm);

    unsigned long long acc[4][8];
#pragma unroll
    for (int p = 0; p < 4; p++)
#pragma unroll
        for (int c = 0; c < 8; c++) acc[p][c] = 0ull;

    GEMM_ISSUE(0);

    // zero the output (streaming stores) — drains under the mainloop
    {
        const float4 z = make_float4(0.f, 0.f, 0.f, 0.f);
        float4* o4 = (float4*)out;
        const size_t total4 = (size_t)NN * NN / 4;
        for (size_t i = (size_t)blockIdx.x * 256 + tid; i < total4;
             i += (size_t)gridDim.x * 256)
            __stcs(&o4[i], z);
    }

    for (int ch = 0; ch < 8; ch++) {
        if (ch < 7) {
            GEMM_ISSUE(ch + 1);
            asm volatile("cp.async.wait_group 1;");
        } else {
            asm volatile("cp.async.wait_group 0;");
        }
        __syncthreads();

        const float* A = sm + (ch & 1) * ABUF;
        const float* B = A + 4096;
#pragma unroll
        for (int k = 0; k < 32; k++) {
            ulonglong2 a01 = *(const ulonglong2*)&A[k * 128 + ty * 8];
            ulonglong2 a23 = *(const ulonglong2*)&A[k * 128 + ty * 8 + 4];
            float4 bv0 = *(const float4*)&B[k * 128 + tx * 8];
            float4 bv1 = *(const float4*)&B[k * 128 + tx * 8 + 4];
            unsigned long long ap[4] = {a01.x, a01.y, a23.x, a23.y};
            unsigned long long bd[8] = {dup2(bv0.x), dup2(bv0.y), dup2(bv0.z), dup2(bv0.w),
                                        dup2(bv1.x), dup2(bv1.y), dup2(bv1.z), dup2(bv1.w)};
#pragma unroll
            for (int c = 0; c < 8; c++)
#pragma unroll
                for (int p = 0; p < 4; p++)
                    fma2(acc[p][c], ap[p], bd[c]);
        }
        __syncthreads();
    }

#pragma unroll
    for (int p = 0; p < 4; p++) {
        float2 u0 = unpk(acc[p][0]), u1 = unpk(acc[p][1]);
        float2 u2 = unpk(acc[p][2]), u3 = unpk(acc[p][3]);
        float2 u4 = unpk(acc[p][4]), u5 = unpk(acc[p][5]);
        float2 u6 = unpk(acc[p][6]), u7 = unpk(acc[p][7]);
        size_t base = (size_t)(rowBase + ty * 8 + 2 * p) * NN + colBase + tx * 8;
        *(float4*)&g_S[base]          = make_float4(u0.x, u1.x, u2.x, u3.x);
        *(float4*)&g_S[base + 4]      = make_float4(u4.x, u5.x, u6.x, u7.x);
        *(float4*)&g_S[base + NN]     = make_float4(u0.y, u1.y, u2.y, u3.y);
        *(float4*)&g_S[base + NN + 4] = make_float4(u4.y, u5.y, u6.y, u7.y);
    }
}

// ---------------------------------------------------------------------------
// Kernel B: ballot-collect the first 32 exact-1.0 columns per row (exact:
// tanh <= 1 and stable top_k prefers lower index). Fallback: generic exact
// streaming top-32 for rows with < 32 saturated entries (probability ~0).
// ---------------------------------------------------------------------------
#define SS_PITCH 132
#define ST_PITCH 68

__device__ void generic_row_topk(int r, float* __restrict__ out) {
    const int lane = threadIdx.x & 31;
    unsigned long long key = 0ull, rmin = 0ull;
    for (int cb = 0; cb < NN; cb += 32) {
        int c = cb + lane;
        float sv, tv;
        if (cb + 32 <= STRIPE_COLS) {
            sv = g_S[(size_t)r * NN + c];
            tv = g_S[(size_t)c * NN + r];
        } else {
            sv = s_compute(r, c);
            tv = s_compute(c, r);
        }
        float v = adj_val(__fsub_rn(sv, tv));
        unsigned long long cand =
            ((unsigned long long)__float_as_uint(v) << 32)
            | (unsigned)(0xFFFFFFFFu - (unsigned)c);
        unsigned m = __ballot_sync(FULLM, cand > rmin);
        while (m) {
            int src = __ffs(m) - 1; m &= m - 1;
            unsigned long long ck = __shfl_sync(FULLM, cand, src);
            if (ck > rmin) {
                unsigned bal = __ballot_sync(FULLM, key == rmin);
                if (lane == (__ffs(bal) - 1)) key = ck;
                unsigned long long mm = key;
#pragma unroll
                for (int o = 16; o > 0; o >>= 1) {
                    unsigned long long om = __shfl_xor_sync(FULLM, mm, o);
                    mm = om < mm ? om : mm;
                }
                rmin = mm;
            }
        }
    }
    unsigned vb = (unsigned)(key >> 32);
    if (vb) {
        unsigned col = 0xFFFFFFFFu - (unsigned)(key & 0xFFFFFFFFull);
        out[(size_t)r * NN + col] = __uint_as_float(vb);
    }
}

__global__ __launch_bounds__(256, 1) void adj_topk2_kernel(float* __restrict__ out) {
    extern __shared__ float sm[];
    float* sS = sm;                            // [64][132]  S[row][col]
    float* sT = sm + 64 * SS_PITCH;            // [128][68]  S[col][row]

    const int rowBase = blockIdx.x * 64;
    const int tid  = threadIdx.x;
    const int lane = tid & 31, wrp = tid >> 5;
    const int sr = tid >> 2, sc = (tid & 3) * 32;
    const int tr = tid >> 1, tcx = (tid & 1) * 32;

    int cnt[8];
    int mycol[8];
#pragma unroll
    for (int q = 0; q < 8; q++) { cnt[q] = 0; mycol[q] = -1; }

    for (int t = 0; t < 64; t++) {
        const int colBase = t * 128;
        if (t < STRIPE_TILES) {
            {
                const float4* src = (const float4*)&g_S[(size_t)(rowBase + sr) * NN + colBase + sc];
                float4* dst = (float4*)&sS[sr * SS_PITCH + sc];
#pragma unroll
                for (int i = 0; i < 8; i++) dst[i] = src[i];
            }
            {
                const float4* src = (const float4*)&g_S[(size_t)(colBase + tr) * NN + rowBase + tcx];
                float4* dst = (float4*)&sT[tr * ST_PITCH + tcx];
#pragma unroll
                for (int i = 0; i < 8; i++) dst[i] = src[i];
            }
        } else {
            for (int e = 0; e < 32; e++)
                sS[sr * SS_PITCH + sc + e] = s_compute(rowBase + sr, colBase + sc + e);
            for (int e = 0; e < 32; e++)
                sT[tr * ST_PITCH + tcx + e] = s_compute(colBase + tr, rowBase + tcx + e);
        }
        __syncthreads();

#pragma unroll
        for (int q = 0; q < 8; q++) {
            if (cnt[q] >= 32) continue;
            const int r = wrp * 8 + q;
#pragma unroll
            for (int s4 = 0; s4 < 4; s4++) {
                const int col = lane + 32 * s4;
                float a = __fsub_rn(sS[r * SS_PITCH + col], sT[col * ST_PITCH + r]);
                float v = adj_val(a);
                unsigned m = __ballot_sync(FULLM, v == 1.0f);
                int avail = __popc(m);
                int nc = min(32 - cnt[q], avail);
                int sl = lane - cnt[q];
                if (sl >= 0 && sl < nc) {
                    int bit = __fns(m, 0, sl + 1);
                    mycol[q] = colBase + 32 * s4 + bit;
                }
                cnt[q] += nc;
                if (cnt[q] >= 32) break;
            }
        }

        bool full = true;
#pragma unroll
        for (int q = 0; q < 8; q++) full &= (cnt[q] >= 32);
        if (__syncthreads_and(full)) break;
    }

#pragma unroll
    for (int q = 0; q < 8; q++) {
        if (cnt[q] >= 32) {
            if (mycol[q] >= 0)
                out[(size_t)(rowBase + wrp * 8 + q) * NN + mycol[q]] = 1.0f;
        } else {
            generic_row_topk(rowBase + wrp * 8 + q, out);
        }
    }
}

// ---------------------------------------------------------------------------
// Inputs (metadata order): idx(int64), scale_idx, scale_set, emb1, emb2,
//                          W1, b1, W2, b2.  Output: float32 [8192*8192].
// ---------------------------------------------------------------------------
extern "C" void kernel_launch(void* const* d_in, const int* in_sizes, int n_in,
                              void* d_out, int out_size) {
    const float* emb1 = (const float*)d_in[3];
    const float* emb2 = (const float*)d_in[4];
    const float* W1   = (const float*)d_in[5];
    const float* b1   = (const float*)d_in[6];
    const float* W2   = (const float*)d_in[7];
    const float* b2   = (const float*)d_in[8];
    float* out = (float*)d_out;

    (void)in_sizes; (void)n_in; (void)out_size;

    static const size_t GEMM_SMEM = 2 * ABUF * sizeof(float);                         // 64KB
    static const size_t ADJ_SMEM  = (64 * SS_PITCH + 128 * ST_PITCH) * sizeof(float); // ~69KB
    cudaFuncSetAttribute(nv_gemm_kernel,
                         cudaFuncAttributeMaxDynamicSharedMemorySize, (int)GEMM_SMEM);
    cudaFuncSetAttribute(s_gemm_kernel,
                         cudaFuncAttributeMaxDynamicSharedMemorySize, (int)GEMM_SMEM);
    cudaFuncSetAttribute(adj_topk2_kernel,
                         cudaFuncAttributeMaxDynamicSharedMemorySize, (int)ADJ_SMEM);

    // 1) exact transposes: embT [k][node], WT [k][col]
    transpose_kernel<<<dim3(DIMK / 32, NN / 32, 4), 256>>>(emb1, emb2, W1, W2);

    // 2) nv GEMM (both sets): nvT = tanh(3*(emb @ W^T + b))^T
    nv_gemm_kernel<<<dim3(NN / 128, DIMK / 128, 2), 256, GEMM_SMEM>>>(b1, b2);

    // 3) stripe GEMM (also zeroes the output under the mainloop)
    s_gemm_kernel<<<64 * STRIPE_TILES + STRIPE_TILES * (64 - STRIPE_TILES),
                    256, GEMM_SMEM>>>(out);

    // 4) top-32 collect + scatter
    adj_topk2_kernel<<<NN / 64, 256, ADJ_SMEM>>>(out);
}

// round 15
// speedup vs baseline: 1.4151x; 1.0060x over previous
#include <cuda_runtime.h>
#include <cstdint>

#define NN   8192
#define DIMK 256
#define FULLM 0xFFFFFFFFu

// XLA EmitTanh f32 clamp constant (validated: rel_err == 0.0)
#define KMAX_TANH 7.99881172180175781f

// Stripe width: per-row saturated count in 256 cols ~ Binom(256,0.41):
// mean 105, sigma 7.9 -> P(<32) ~ 1e-20. Cold path backstops correctness.
#define STRIPE_TILES 2            // 2 tiles x 128 cols = 256
#define STRIPE_COLS  (STRIPE_TILES * 128)

// Scratch (device globals — no allocation allowed)
__device__ float g_e1t[DIMK * NN];             // emb1^T  [k][node]
__device__ float g_e2t[DIMK * NN];             // emb2^T
__device__ float g_w1t[DIMK * DIMK];           // W1^T    [k][col]
__device__ float g_w2t[DIMK * DIMK];           // W2^T
__device__ float g_nv1t[DIMK * NN];            // nv1^T   [k][node]
__device__ float g_nv2t[DIMK * NN];            // nv2^T
__device__ float g_Srow[(size_t)NN * STRIPE_COLS];  // S[r][c], c<256   (8MB)
__device__ float g_Trow[(size_t)NN * STRIPE_COLS];  // T[r][c]=S[c][r]  (8MB)

// ---------------------------------------------------------------------------
// Eigen/XLA rational tanh (fma Horner), clamped at +/-KMAX_TANH.
// ---------------------------------------------------------------------------
__device__ __forceinline__ float tanh_nv(float x) {
    float t = fminf(fmaxf(x, -KMAX_TANH), KMAX_TANH);
    float x2 = __fmul_rn(t, t);
    float p = fmaf(x2, -2.76076847742355e-16f, 2.00018790482477e-13f);
    p = fmaf(x2, p, -8.60467152213735e-11f);
    p = fmaf(x2, p,  5.12229709037114e-08f);
    p = fmaf(x2, p,  1.48572235717979e-05f);
    p = fmaf(x2, p,  6.37261928875436e-04f);
    p = fmaf(x2, p,  4.89352455891786e-03f);
    p = __fmul_rn(t, p);
    float q = fmaf(x2, 1.19825839466702e-06f, 1.18534705686654e-04f);
    q = fmaf(x2, q, 2.26843463243900e-03f);
    q = fmaf(x2, q, 4.89352518554385e-03f);
    float r = __fdiv_rn(p, q);
    return (fabsf(x) < 0.0004f) ? x : r;
}

// relu(tanh(3a)) with the decision boundary explicit (tie class == 1.0f).
__device__ __forceinline__ float adj_val(float a) {
    float x = __fmul_rn(3.0f, a);
    if (x >= KMAX_TANH) return 1.0f;
    if (x <= 0.0f)      return 0.0f;
    float x2 = __fmul_rn(x, x);
    float p = fmaf(x2, -2.76076847742355e-16f, 2.00018790482477e-13f);
    p = fmaf(x2, p, -8.60467152213735e-11f);
    p = fmaf(x2, p,  5.12229709037114e-08f);
    p = fmaf(x2, p,  1.48572235717979e-05f);
    p = fmaf(x2, p,  6.37261928875436e-04f);
    p = fmaf(x2, p,  4.89352455891786e-03f);
    p = __fmul_rn(x, p);
    float q = fmaf(x2, 1.19825839466702e-06f, 1.18534705686654e-04f);
    q = fmaf(x2, q, 2.26843463243900e-03f);
    q = fmaf(x2, q, 4.89352518554385e-03f);
    float r = __fdiv_rn(p, q);
    return (x < 0.0004f) ? x : r;
}

// Packed f32x2 helpers (each lane rounds exactly like a scalar FFMA)
__device__ __forceinline__ unsigned long long dup2(float x) {
    unsigned long long r;
    asm("mov.b64 %0, {%1, %1};" : "=l"(r) : "f"(x));
    return r;
}
__device__ __forceinline__ void fma2(unsigned long long& d,
                                     unsigned long long a,
                                     unsigned long long b) {
    asm("fma.rn.f32x2 %0, %1, %2, %0;" : "+l"(d) : "l"(a), "l"(b));
}
__device__ __forceinline__ float2 unpk(unsigned long long v) {
    float2 f;
    asm("mov.b64 {%0, %1}, %2;" : "=f"(f.x), "=f"(f.y) : "l"(v));
    return f;
}

__device__ __forceinline__ void cpasync16(uint32_t dst, const float* src) {
    asm volatile("cp.async.cg.shared.global [%0], [%1], 16;" :: "r"(dst), "l"(src));
}

// Cold-path recompute: identical ascending-k fmaf chains.
__device__ __forceinline__ float s_compute(int r, int c) {        // S[r][c]
    float acc = 0.0f;
    for (int k = 0; k < DIMK; k++)
        acc = fmaf(g_nv1t[(size_t)k * NN + r], g_nv2t[(size_t)k * NN + c], acc);
    return acc;
}
__device__ __forceinline__ float t_compute(int r, int c) {        // T[r][c]=S[c][r]
    float acc = 0.0f;
    for (int k = 0; k < DIMK; k++)
        acc = fmaf(g_nv2t[(size_t)k * NN + r], g_nv1t[(size_t)k * NN + c], acc);
    return acc;
}

// ---------------------------------------------------------------------------
// Transpose pre-pass (exact copies). Grid (8, 264, 2): y<256 -> emb tile,
// y>=256 -> W tile; z selects set 1/2. No dead blocks.
// ---------------------------------------------------------------------------
__global__ __launch_bounds__(256) void transpose_kernel(const float* __restrict__ e1,
                                                        const float* __restrict__ e2,
                                                        const float* __restrict__ w1,
                                                        const float* __restrict__ w2) {
    __shared__ float tile[32][33];
    const int z = blockIdx.z;
    const int yy = blockIdx.y;
    const float* src;
    float* dst;
    int R, by;
    if (yy < 256) { src = z ? e2 : e1; dst = z ? g_e2t : g_e1t; R = NN;   by = yy * 32; }
    else          { src = z ? w2 : w1; dst = z ? g_w2t : g_w1t; R = DIMK; by = (yy - 256) * 32; }
    const int bx = blockIdx.x * 32;

    const int tx = threadIdx.x & 31, ty = threadIdx.x >> 5;
#pragma unroll
    for (int i = ty; i < 32; i += 8)
        tile[i][tx] = src[(size_t)(by + i) * DIMK + bx + tx];
    __syncthreads();
#pragma unroll
    for (int i = ty; i < 32; i += 8)
        dst[(size_t)(bx + i) * R + by + tx] = tile[tx][i];
}

// ---------------------------------------------------------------------------
// nv GEMM (validated 213us shape): nvT = tanh(3*(emb @ W^T + b))^T.
// 256 threads, 8x8 thread tile, cp.async double buffer, fma2 row pairs.
// ---------------------------------------------------------------------------
#define ABUF 8192   // floats per buffer: A tile 4096 + B tile 4096

#define NV_ISSUE(ch)                                                           \
    do {                                                                       \
        int _buf = (ch) & 1;                                                   \
        const float* _a = &At[(size_t)((ch) * 32 + lk) * NN + rowBase + lo];   \
        const float* _b = &Bt[(size_t)((ch) * 32 + lk) * DIMK + colBase + lo]; \
        uint32_t _da = smb + (uint32_t)(_buf * ABUF + lk * 128 + lo) * 4u;     \
        uint32_t _db = _da + 4096u * 4u;                                       \
        cpasync16(_da,      _a);     cpasync16(_da + 16, _a + 4);              \
        cpasync16(_da + 32, _a + 8); cpasync16(_da + 48, _a + 12);             \
        cpasync16(_db,      _b);     cpasync16(_db + 16, _b + 4);              \
        cpasync16(_db + 32, _b + 8); cpasync16(_db + 48, _b + 12);             \
        asm volatile("cp.async.commit_group;");                                \
    } while (0)

__global__ __launch_bounds__(256, 2) void nv_gemm_kernel(const float* __restrict__ b1,
                                                         const float* __restrict__ b2) {
    extern __shared__ float sm[];
    const int tid = threadIdx.x;
    const int sel = blockIdx.z;
    const float* At   = sel ? g_e2t : g_e1t;
    const float* Bt   = sel ? g_w2t : g_w1t;
    const float* bias = sel ? b2 : b1;
    float* nvT = sel ? g_nv2t : g_nv1t;

    const int rowBase = blockIdx.x * 128;
    const int colBase = blockIdx.y * 128;
    const int ty = tid & 15;
    const int tx = tid >> 4;
    const int lk = tid >> 3;
    const int lo = (tid & 7) * 16;
    const uint32_t smb = (uint32_t)__cvta_generic_to_shared(sm);

    unsigned long long acc[4][8];
#pragma unroll
    for (int p = 0; p < 4; p++)
#pragma unroll
        for (int c = 0; c < 8; c++) acc[p][c] = 0ull;

    NV_ISSUE(0);
    for (int ch = 0; ch < 8; ch++) {
        if (ch < 7) {
            NV_ISSUE(ch + 1);
            asm volatile("cp.async.wait_group 1;");
        } else {
            asm volatile("cp.async.wait_group 0;");
        }
        __syncthreads();

        const float* A = sm + (ch & 1) * ABUF;
        const float* B = A + 4096;
#pragma unroll
        for (int k = 0; k < 32; k++) {
            ulonglong2 a01 = *(const ulonglong2*)&A[k * 128 + ty * 8];
            ulonglong2 a23 = *(const ulonglong2*)&A[k * 128 + ty * 8 + 4];
            float4 bv0 = *(const float4*)&B[k * 128 + tx * 8];
            float4 bv1 = *(const float4*)&B[k * 128 + tx * 8 + 4];
            unsigned long long ap[4] = {a01.x, a01.y, a23.x, a23.y};
            unsigned long long bd[8] = {dup2(bv0.x), dup2(bv0.y), dup2(bv0.z), dup2(bv0.w),
                                        dup2(bv1.x), dup2(bv1.y), dup2(bv1.z), dup2(bv1.w)};
#pragma unroll
            for (int c = 0; c < 8; c++)
#pragma unroll
                for (int p = 0; p < 4; p++)
                    fma2(acc[p][c], ap[p], bd[c]);
        }
        __syncthreads();
    }

    // epilogue: y = 3*(acc+b) (unfused add then mul), tanh, store transposed.
#pragma unroll
    for (int c = 0; c < 8; c++) {
        const int col = colBase + tx * 8 + c;
        const float b = bias[col];
        float2 v01 = unpk(acc[0][c]), v23 = unpk(acc[1][c]);
        float2 v45 = unpk(acc[2][c]), v67 = unpk(acc[3][c]);
        float4 o0, o1;
        o0.x = tanh_nv(__fmul_rn(3.0f, __fadd_rn(v01.x, b)));
        o0.y = tanh_nv(__fmul_rn(3.0f, __fadd_rn(v01.y, b)));
        o0.z = tanh_nv(__fmul_rn(3.0f, __fadd_rn(v23.x, b)));
        o0.w = tanh_nv(__fmul_rn(3.0f, __fadd_rn(v23.y, b)));
        o1.x = tanh_nv(__fmul_rn(3.0f, __fadd_rn(v45.x, b)));
        o1.y = tanh_nv(__fmul_rn(3.0f, __fadd_rn(v45.y, b)));
        o1.z = tanh_nv(__fmul_rn(3.0f, __fadd_rn(v67.x, b)));
        o1.w = tanh_nv(__fmul_rn(3.0f, __fadd_rn(v67.y, b)));
        size_t base = (size_t)col * NN + rowBase + ty * 8;
        *(float4*)&nvT[base]     = o0;
        *(float4*)&nvT[base + 4] = o1;
    }
}

// ---------------------------------------------------------------------------
// Kernel A: dual row-stripe GEMM.  256 CTAs:
//   bid <  128:  S[r][c] = sum_k nv1t[k][r]*nv2t[k][c]  -> g_Srow (all rows x cols 0..255)
//   bid >= 128:  T[r][c] = sum_k nv2t[k][r]*nv1t[k][c]  -> g_Trow (== S[c][r], bitwise:
//                mul commutes exactly; same ascending-k single-accumulator chain)
// Also zeroes the 256MB output with streaming stores under the FMA mainloop.
// ---------------------------------------------------------------------------
#define GEMM_ISSUE(ch)                                                         \
    do {                                                                       \
        int _buf = (ch) & 1;                                                   \
        const float* _a = &At[(size_t)((ch) * 32 + lk) * NN + rowBase + lo];   \
        const float* _b = &Bt[(size_t)((ch) * 32 + lk) * NN + colBase + lo];   \
        uint32_t _da = smb + (uint32_t)(_buf * ABUF + lk * 128 + lo) * 4u;     \
        uint32_t _db = _da + 4096u * 4u;                                       \
        cpasync16(_da,      _a);     cpasync16(_da + 16, _a + 4);              \
        cpasync16(_da + 32, _a + 8); cpasync16(_da + 48, _a + 12);             \
        cpasync16(_db,      _b);     cpasync16(_db + 16, _b + 4);              \
        cpasync16(_db + 32, _b + 8); cpasync16(_db + 48, _b + 12);             \
        asm volatile("cp.async.commit_group;");                                \
    } while (0)

__global__ __launch_bounds__(256, 2) void s_gemm_kernel(float* __restrict__ out) {
    extern __shared__ float sm[];
    const int tid = threadIdx.x;

    const int bid  = blockIdx.x;          // 0..255
    const int half = bid >> 7;            // 0: S, 1: T
    const int b    = bid & 127;
    const int rowBase = (b >> 1) * 128;
    const int colBase = (b & 1) * 128;
    const float* At = half ? g_nv2t : g_nv1t;
    const float* Bt = half ? g_nv1t : g_nv2t;
    float* Out      = half ? g_Trow : g_Srow;

    const int ty = tid & 15;
    const int tx = tid >> 4;
    const int lk = tid >> 3;
    const int lo = (tid & 7) * 16;
    const uint32_t smb = (uint32_t)__cvta_generic_to_shared(sm);

    unsigned long long acc[4][8];
#pragma unroll
    for (int p = 0; p < 4; p++)
#pragma unroll
        for (int c = 0; c < 8; c++) acc[p][c] = 0ull;

    GEMM_ISSUE(0);

    // zero the output (streaming stores) — drains under the mainloop
    {
        const float4 z = make_float4(0.f, 0.f, 0.f, 0.f);
        float4* o4 = (float4*)out;
        const size_t total4 = (size_t)NN * NN / 4;
        for (size_t i = (size_t)blockIdx.x * 256 + tid; i < total4;
             i += (size_t)gridDim.x * 256)
            __stcs(&o4[i], z);
    }

    for (int ch = 0; ch < 8; ch++) {
        if (ch < 7) {
            GEMM_ISSUE(ch + 1);
            asm volatile("cp.async.wait_group 1;");
        } else {
            asm volatile("cp.async.wait_group 0;");
        }
        __syncthreads();

        const float* A = sm + (ch & 1) * ABUF;
        const float* B = A + 4096;
#pragma unroll
        for (int k = 0; k < 32; k++) {
            ulonglong2 a01 = *(const ulonglong2*)&A[k * 128 + ty * 8];
            ulonglong2 a23 = *(const ulonglong2*)&A[k * 128 + ty * 8 + 4];
            float4 bv0 = *(const float4*)&B[k * 128 + tx * 8];
            float4 bv1 = *(const float4*)&B[k * 128 + tx * 8 + 4];
            unsigned long long ap[4] = {a01.x, a01.y, a23.x, a23.y};
            unsigned long long bd[8] = {dup2(bv0.x), dup2(bv0.y), dup2(bv0.z), dup2(bv0.w),
                                        dup2(bv1.x), dup2(bv1.y), dup2(bv1.z), dup2(bv1.w)};
#pragma unroll
            for (int c = 0; c < 8; c++)
#pragma unroll
                for (int p = 0; p < 4; p++)
                    fma2(acc[p][c], ap[p], bd[c]);
        }
        __syncthreads();
    }

    // epilogue: compact stripe buffer, row pitch STRIPE_COLS
#pragma unroll
    for (int p = 0; p < 4; p++) {
        float2 u0 = unpk(acc[p][0]), u1 = unpk(acc[p][1]);
        float2 u2 = unpk(acc[p][2]), u3 = unpk(acc[p][3]);
        float2 u4 = unpk(acc[p][4]), u5 = unpk(acc[p][5]);
        float2 u6 = unpk(acc[p][6]), u7 = unpk(acc[p][7]);
        size_t base = (size_t)(rowBase + ty * 8 + 2 * p) * STRIPE_COLS + colBase + tx * 8;
        *(float4*)&Out[base]               = make_float4(u0.x, u1.x, u2.x, u3.x);
        *(float4*)&Out[base + 4]           = make_float4(u4.x, u5.x, u6.x, u7.x);
        *(float4*)&Out[base + STRIPE_COLS]     = make_float4(u0.y, u1.y, u2.y, u3.y);
        *(float4*)&Out[base + STRIPE_COLS + 4] = make_float4(u4.y, u5.y, u6.y, u7.y);
    }
}

// ---------------------------------------------------------------------------
// Kernel B: ballot-collect the first 32 exact-1.0 columns per row (exact:
// tanh <= 1 and stable top_k prefers lower index). Both stripe tiles are now
// row-major coalesced loads from compact buffers. Fallback: generic exact
// streaming top-32 (probability ~0), backed by s_compute/t_compute.
// ---------------------------------------------------------------------------
#define SS_PITCH 132

__device__ void generic_row_topk(int r, float* __restrict__ out) {
    const int lane = threadIdx.x & 31;
    unsigned long long key = 0ull, rmin = 0ull;
    for (int cb = 0; cb < NN; cb += 32) {
        int c = cb + lane;
        float sv, tv;
        if (cb + 32 <= STRIPE_COLS) {
            sv = g_Srow[(size_t)r * STRIPE_COLS + c];
            tv = g_Trow[(size_t)r * STRIPE_COLS + c];
        } else {
            sv = s_compute(r, c);
            tv = t_compute(r, c);
        }
        float v = adj_val(__fsub_rn(sv, tv));
        unsigned long long cand =
            ((unsigned long long)__float_as_uint(v) << 32)
            | (unsigned)(0xFFFFFFFFu - (unsigned)c);
        unsigned m = __ballot_sync(FULLM, cand > rmin);
        while (m) {
            int src = __ffs(m) - 1; m &= m - 1;
            unsigned long long ck = __shfl_sync(FULLM, cand, src);
            if (ck > rmin) {
                unsigned bal = __ballot_sync(FULLM, key == rmin);
                if (lane == (__ffs(bal) - 1)) key = ck;
                unsigned long long mm = key;
#pragma unroll
                for (int o = 16; o > 0; o >>= 1) {
                    unsigned long long om = __shfl_xor_sync(FULLM, mm, o);
                    mm = om < mm ? om : mm;
                }
                rmin = mm;
            }
        }
    }
    unsigned vb = (unsigned)(key >> 32);
    if (vb) {
        unsigned col = 0xFFFFFFFFu - (unsigned)(key & 0xFFFFFFFFull);
        out[(size_t)r * NN + col] = __uint_as_float(vb);
    }
}

__global__ __launch_bounds__(256, 1) void adj_topk2_kernel(float* __restrict__ out) {
    extern __shared__ float sm[];
    float* sS = sm;                            // [64][132]  S[row][col]
    float* sT = sm + 64 * SS_PITCH;            // [64][132]  T[row][col]

    const int rowBase = blockIdx.x * 64;
    const int tid  = threadIdx.x;
    const int lane = tid & 31, wrp = tid >> 5;
    const int sr = tid >> 2, sc = (tid & 3) * 32;    // 64 rows x 4 chunks of 32

    int cnt[8];
    int mycol[8];
#pragma unroll
    for (int q = 0; q < 8; q++) { cnt[q] = 0; mycol[q] = -1; }

    for (int t = 0; t < 64; t++) {
        const int colBase = t * 128;
        if (t < STRIPE_TILES) {
            {
                const float4* srcS = (const float4*)&g_Srow[(size_t)(rowBase + sr) * STRIPE_COLS + colBase + sc];
                const float4* srcT = (const float4*)&g_Trow[(size_t)(rowBase + sr) * STRIPE_COLS + colBase + sc];
                float4* dstS = (float4*)&sS[sr * SS_PITCH + sc];
                float4* dstT = (float4*)&sT[sr * SS_PITCH + sc];
#pragma unroll
                for (int i = 0; i < 8; i++) { dstS[i] = srcS[i]; dstT[i] = srcT[i]; }
            }
        } else {
            // cold path: exact recompute (identical chains); probability ~0
            for (int e = 0; e < 32; e++) {
                sS[sr * SS_PITCH + sc + e] = s_compute(rowBase + sr, colBase + sc + e);
                sT[sr * SS_PITCH + sc + e] = t_compute(rowBase + sr, colBase + sc + e);
            }
        }
        __syncthreads();

        // ballot-collect exact-1.0 columns (warp w owns rows w*8..w*8+7)
#pragma unroll
        for (int q = 0; q < 8; q++) {
            if (cnt[q] >= 32) continue;
            const int r = wrp * 8 + q;
#pragma unroll
            for (int s4 = 0; s4 < 4; s4++) {
                const int col = lane + 32 * s4;
                float a = __fsub_rn(sS[r * SS_PITCH + col], sT[r * SS_PITCH + col]);
                float v = adj_val(a);
                unsigned m = __ballot_sync(FULLM, v == 1.0f);
                int avail = __popc(m);
                int nc = min(32 - cnt[q], avail);
                int sl = lane - cnt[q];
                if (sl >= 0 && sl < nc) {
                    int bit = __fns(m, 0, sl + 1);
                    mycol[q] = colBase + 32 * s4 + bit;
                }
                cnt[q] += nc;
                if (cnt[q] >= 32) break;
            }
        }

        bool full = true;
#pragma unroll
        for (int q = 0; q < 8; q++) full &= (cnt[q] >= 32);
        if (__syncthreads_and(full)) break;
    }

    // scatter (output pre-zeroed; every collected value is exactly 1.0f)
#pragma unroll
    for (int q = 0; q < 8; q++) {
        if (cnt[q] >= 32) {
            if (mycol[q] >= 0)
                out[(size_t)(rowBase + wrp * 8 + q) * NN + mycol[q]] = 1.0f;
        } else {
            generic_row_topk(rowBase + wrp * 8 + q, out);
        }
    }
}

// ---------------------------------------------------------------------------
// Inputs (metadata order): idx(int64), scale_idx, scale_set, emb1, emb2,
//                          W1, b1, W2, b2.  Output: float32 [8192*8192].
// ---------------------------------------------------------------------------
extern "C" void kernel_launch(void* const* d_in, const int* in_sizes, int n_in,
                              void* d_out, int out_size) {
    const float* emb1 = (const float*)d_in[3];
    const float* emb2 = (const float*)d_in[4];
    const float* W1   = (const float*)d_in[5];
    const float* b1   = (const float*)d_in[6];
    const float* W2   = (const float*)d_in[7];
    const float* b2   = (const float*)d_in[8];
    float* out = (float*)d_out;

    (void)in_sizes; (void)n_in; (void)out_size;

    static const size_t GEMM_SMEM = 2 * ABUF * sizeof(float);            // 64KB
    static const size_t ADJ_SMEM  = 2 * 64 * SS_PITCH * sizeof(float);   // ~66KB
    cudaFuncSetAttribute(nv_gemm_kernel,
                         cudaFuncAttributeMaxDynamicSharedMemorySize, (int)GEMM_SMEM);
    cudaFuncSetAttribute(s_gemm_kernel,
                         cudaFuncAttributeMaxDynamicSharedMemorySize, (int)GEMM_SMEM);
    cudaFuncSetAttribute(adj_topk2_kernel,
                         cudaFuncAttributeMaxDynamicSharedMemorySize, (int)ADJ_SMEM);

    // 1) exact transposes: embT [k][node], WT [k][col] (no dead blocks)
    transpose_kernel<<<dim3(DIMK / 32, 264, 2), 256>>>(emb1, emb2, W1, W2);

    // 2) nv GEMM (both sets): nvT = tanh(3*(emb @ W^T + b))^T
    nv_gemm_kernel<<<dim3(NN / 128, DIMK / 128, 2), 256, GEMM_SMEM>>>(b1, b2);

    // 3) dual row-stripe GEMM (S and T) + output zeroing under the mainloop
    s_gemm_kernel<<<256, 256, GEMM_SMEM>>>(out);

    // 4) top-32 collect + scatter
    adj_topk2_kernel<<<NN / 64, 256, ADJ_SMEM>>>(out);
}

// round 16
// speedup vs baseline: 1.4581x; 1.0304x over previous
#include <cuda_runtime.h>
#include <cstdint>

#define NN   8192
#define DIMK 256
#define FULLM 0xFFFFFFFFu

// XLA EmitTanh f32 clamp constant (validated: rel_err == 0.0)
#define KMAX_TANH 7.99881172180175781f

// Stripe width: per-row saturated count in 256 cols ~ Binom(256,0.41):
// mean 105, sigma 7.9 -> P(<32) ~ 1e-20. Cold path backstops correctness.
#define STRIPE_TILES 2            // 2 tiles x 128 cols = 256
#define STRIPE_COLS  (STRIPE_TILES * 128)

// Scratch (device globals — no allocation allowed)
__device__ float g_e1t[DIMK * NN];             // emb1^T  [k][node]
__device__ float g_e2t[DIMK * NN];             // emb2^T
__device__ float g_w1t[DIMK * DIMK];           // W1^T    [k][col]
__device__ float g_w2t[DIMK * DIMK];           // W2^T
__device__ float g_nv1t[DIMK * NN];            // nv1^T   [k][node]
__device__ float g_nv2t[DIMK * NN];            // nv2^T
__device__ float g_Srow[(size_t)NN * STRIPE_COLS];  // S[r][c], c<256   (8MB)
__device__ float g_Trow[(size_t)NN * STRIPE_COLS];  // T[r][c]=S[c][r]  (8MB)

// ---------------------------------------------------------------------------
// Eigen/XLA rational tanh (fma Horner), clamped at +/-KMAX_TANH.
// ---------------------------------------------------------------------------
__device__ __forceinline__ float tanh_nv(float x) {
    float t = fminf(fmaxf(x, -KMAX_TANH), KMAX_TANH);
    float x2 = __fmul_rn(t, t);
    float p = fmaf(x2, -2.76076847742355e-16f, 2.00018790482477e-13f);
    p = fmaf(x2, p, -8.60467152213735e-11f);
    p = fmaf(x2, p,  5.12229709037114e-08f);
    p = fmaf(x2, p,  1.48572235717979e-05f);
    p = fmaf(x2, p,  6.37261928875436e-04f);
    p = fmaf(x2, p,  4.89352455891786e-03f);
    p = __fmul_rn(t, p);
    float q = fmaf(x2, 1.19825839466702e-06f, 1.18534705686654e-04f);
    q = fmaf(x2, q, 2.26843463243900e-03f);
    q = fmaf(x2, q, 4.89352518554385e-03f);
    float r = __fdiv_rn(p, q);
    return (fabsf(x) < 0.0004f) ? x : r;
}

// relu(tanh(3a)) with the decision boundary explicit (tie class == 1.0f).
__device__ __forceinline__ float adj_val(float a) {
    float x = __fmul_rn(3.0f, a);
    if (x >= KMAX_TANH) return 1.0f;
    if (x <= 0.0f)      return 0.0f;
    float x2 = __fmul_rn(x, x);
    float p = fmaf(x2, -2.76076847742355e-16f, 2.00018790482477e-13f);
    p = fmaf(x2, p, -8.60467152213735e-11f);
    p = fmaf(x2, p,  5.12229709037114e-08f);
    p = fmaf(x2, p,  1.48572235717979e-05f);
    p = fmaf(x2, p,  6.37261928875436e-04f);
    p = fmaf(x2, p,  4.89352455891786e-03f);
    p = __fmul_rn(x, p);
    float q = fmaf(x2, 1.19825839466702e-06f, 1.18534705686654e-04f);
    q = fmaf(x2, q, 2.26843463243900e-03f);
    q = fmaf(x2, q, 4.89352518554385e-03f);
    float r = __fdiv_rn(p, q);
    return (x < 0.0004f) ? x : r;
}

// Packed f32x2 helpers (each lane rounds exactly like a scalar FFMA)
__device__ __forceinline__ unsigned long long dup2(float x) {
    unsigned long long r;
    asm("mov.b64 %0, {%1, %1};" : "=l"(r) : "f"(x));
    return r;
}
__device__ __forceinline__ void fma2(unsigned long long& d,
                                     unsigned long long a,
                                     unsigned long long b) {
    asm("fma.rn.f32x2 %0, %1, %2, %0;" : "+l"(d) : "l"(a), "l"(b));
}
__device__ __forceinline__ float2 unpk(unsigned long long v) {
    float2 f;
    asm("mov.b64 {%0, %1}, %2;" : "=f"(f.x), "=f"(f.y) : "l"(v));
    return f;
}

__device__ __forceinline__ void cpasync16(uint32_t dst, const float* src) {
    asm volatile("cp.async.cg.shared.global [%0], [%1], 16;" :: "r"(dst), "l"(src));
}

// Cold-path recompute: identical ascending-k fmaf chains.
__device__ __forceinline__ float s_compute(int r, int c) {        // S[r][c]
    float acc = 0.0f;
    for (int k = 0; k < DIMK; k++)
        acc = fmaf(g_nv1t[(size_t)k * NN + r], g_nv2t[(size_t)k * NN + c], acc);
    return acc;
}
__device__ __forceinline__ float t_compute(int r, int c) {        // T[r][c]=S[c][r]
    float acc = 0.0f;
    for (int k = 0; k < DIMK; k++)
        acc = fmaf(g_nv2t[(size_t)k * NN + r], g_nv1t[(size_t)k * NN + c], acc);
    return acc;
}

// ---------------------------------------------------------------------------
// Transpose pre-pass (exact copies). Grid (8, 264, 2): y<256 -> emb tile,
// y>=256 -> W tile; z selects set 1/2. No dead blocks.
// ---------------------------------------------------------------------------
__global__ __launch_bounds__(256) void transpose_kernel(const float* __restrict__ e1,
                                                        const float* __restrict__ e2,
                                                        const float* __restrict__ w1,
                                                        const float* __restrict__ w2) {
    __shared__ float tile[32][33];
    const int z = blockIdx.z;
    const int yy = blockIdx.y;
    const float* src;
    float* dst;
    int R, by;
    if (yy < 256) { src = z ? e2 : e1; dst = z ? g_e2t : g_e1t; R = NN;   by = yy * 32; }
    else          { src = z ? w2 : w1; dst = z ? g_w2t : g_w1t; R = DIMK; by = (yy - 256) * 32; }
    const int bx = blockIdx.x * 32;

    const int tx = threadIdx.x & 31, ty = threadIdx.x >> 5;
#pragma unroll
    for (int i = ty; i < 32; i += 8)
        tile[i][tx] = src[(size_t)(by + i) * DIMK + bx + tx];
    __syncthreads();
#pragma unroll
    for (int i = ty; i < 32; i += 8)
        dst[(size_t)(bx + i) * R + by + tx] = tile[tx][i];
}

// ---------------------------------------------------------------------------
// nv GEMM (validated shape): nvT = tanh(3*(emb @ W^T + b))^T.
// 256 threads, 8x8 thread tile, cp.async double buffer, fma2 row pairs.
// ---------------------------------------------------------------------------
#define ABUF 8192   // floats per buffer: A tile 4096 + B tile 4096

#define NV_ISSUE(ch)                                                           \
    do {                                                                       \
        int _buf = (ch) & 1;                                                   \
        const float* _a = &At[(size_t)((ch) * 32 + lk) * NN + rowBase + lo];   \
        const float* _b = &Bt[(size_t)((ch) * 32 + lk) * DIMK + colBase + lo]; \
        uint32_t _da = smb + (uint32_t)(_buf * ABUF + lk * 128 + lo) * 4u;     \
        uint32_t _db = _da + 4096u * 4u;                                       \
        cpasync16(_da,      _a);     cpasync16(_da + 16, _a + 4);              \
        cpasync16(_da + 32, _a + 8); cpasync16(_da + 48, _a + 12);             \
        cpasync16(_db,      _b);     cpasync16(_db + 16, _b + 4);              \
        cpasync16(_db + 32, _b + 8); cpasync16(_db + 48, _b + 12);             \
        asm volatile("cp.async.commit_group;");                                \
    } while (0)

__global__ __launch_bounds__(256, 2) void nv_gemm_kernel(const float* __restrict__ b1,
                                                         const float* __restrict__ b2) {
    extern __shared__ float sm[];
    const int tid = threadIdx.x;
    const int sel = blockIdx.z;
    const float* At   = sel ? g_e2t : g_e1t;
    const float* Bt   = sel ? g_w2t : g_w1t;
    const float* bias = sel ? b2 : b1;
    float* nvT = sel ? g_nv2t : g_nv1t;

    const int rowBase = blockIdx.x * 128;
    const int colBase = blockIdx.y * 128;
    const int ty = tid & 15;
    const int tx = tid >> 4;
    const int lk = tid >> 3;
    const int lo = (tid & 7) * 16;
    const uint32_t smb = (uint32_t)__cvta_generic_to_shared(sm);

    unsigned long long acc[4][8];
#pragma unroll
    for (int p = 0; p < 4; p++)
#pragma unroll
        for (int c = 0; c < 8; c++) acc[p][c] = 0ull;

    NV_ISSUE(0);
    for (int ch = 0; ch < 8; ch++) {
        if (ch < 7) {
            NV_ISSUE(ch + 1);
            asm volatile("cp.async.wait_group 1;");
        } else {
            asm volatile("cp.async.wait_group 0;");
        }
        __syncthreads();

        const float* A = sm + (ch & 1) * ABUF;
        const float* B = A + 4096;
#pragma unroll
        for (int k = 0; k < 32; k++) {
            ulonglong2 a01 = *(const ulonglong2*)&A[k * 128 + ty * 8];
            ulonglong2 a23 = *(const ulonglong2*)&A[k * 128 + ty * 8 + 4];
            float4 bv0 = *(const float4*)&B[k * 128 + tx * 8];
            float4 bv1 = *(const float4*)&B[k * 128 + tx * 8 + 4];
            unsigned long long ap[4] = {a01.x, a01.y, a23.x, a23.y};
            unsigned long long bd[8] = {dup2(bv0.x), dup2(bv0.y), dup2(bv0.z), dup2(bv0.w),
                                        dup2(bv1.x), dup2(bv1.y), dup2(bv1.z), dup2(bv1.w)};
#pragma unroll
            for (int c = 0; c < 8; c++)
#pragma unroll
                for (int p = 0; p < 4; p++)
                    fma2(acc[p][c], ap[p], bd[c]);
        }
        __syncthreads();
    }

    // epilogue: y = 3*(acc+b) (unfused add then mul), tanh, store transposed.
#pragma unroll
    for (int c = 0; c < 8; c++) {
        const int col = colBase + tx * 8 + c;
        const float b = bias[col];
        float2 v01 = unpk(acc[0][c]), v23 = unpk(acc[1][c]);
        float2 v45 = unpk(acc[2][c]), v67 = unpk(acc[3][c]);
        float4 o0, o1;
        o0.x = tanh_nv(__fmul_rn(3.0f, __fadd_rn(v01.x, b)));
        o0.y = tanh_nv(__fmul_rn(3.0f, __fadd_rn(v01.y, b)));
        o0.z = tanh_nv(__fmul_rn(3.0f, __fadd_rn(v23.x, b)));
        o0.w = tanh_nv(__fmul_rn(3.0f, __fadd_rn(v23.y, b)));
        o1.x = tanh_nv(__fmul_rn(3.0f, __fadd_rn(v45.x, b)));
        o1.y = tanh_nv(__fmul_rn(3.0f, __fadd_rn(v45.y, b)));
        o1.z = tanh_nv(__fmul_rn(3.0f, __fadd_rn(v67.x, b)));
        o1.w = tanh_nv(__fmul_rn(3.0f, __fadd_rn(v67.y, b)));
        size_t base = (size_t)col * NN + rowBase + ty * 8;
        *(float4*)&nvT[base]     = o0;
        *(float4*)&nvT[base + 4] = o1;
    }
}

// ---------------------------------------------------------------------------
// Kernel A: dual row-stripe GEMM.  256 CTAs:
//   bid <  128:  S[r][c] = sum_k nv1t[k][r]*nv2t[k][c]  -> g_Srow
//   bid >= 128:  T[r][c] = sum_k nv2t[k][r]*nv1t[k][c]  -> g_Trow (== S[c][r]
//                bitwise: mul commutes; same ascending-k chain)
// Also zeroes the 256MB output with streaming stores under the FMA mainloop.
// ---------------------------------------------------------------------------
#define GEMM_ISSUE(ch)                                                         \
    do {                                                                       \
        int _buf = (ch) & 1;                                                   \
        const float* _a = &At[(size_t)((ch) * 32 + lk) * NN + rowBase + lo];   \
        const float* _b = &Bt[(size_t)((ch) * 32 + lk) * NN + colBase + lo];   \
        uint32_t _da = smb + (uint32_t)(_buf * ABUF + lk * 128 + lo) * 4u;     \
        uint32_t _db = _da + 4096u * 4u;                                       \
        cpasync16(_da,      _a);     cpasync16(_da + 16, _a + 4);              \
        cpasync16(_da + 32, _a + 8); cpasync16(_da + 48, _a + 12);             \
        cpasync16(_db,      _b);     cpasync16(_db + 16, _b + 4);              \
        cpasync16(_db + 32, _b + 8); cpasync16(_db + 48, _b + 12);             \
        asm volatile("cp.async.commit_group;");                                \
    } while (0)

__global__ __launch_bounds__(256, 2) void s_gemm_kernel(float* __restrict__ out) {
    extern __shared__ float sm[];
    const int tid = threadIdx.x;

    const int bid  = blockIdx.x;          // 0..255
    const int half = bid >> 7;            // 0: S, 1: T
    const int b    = bid & 127;
    const int rowBase = (b >> 1) * 128;
    const int colBase = (b & 1) * 128;
    const float* At = half ? g_nv2t : g_nv1t;
    const float* Bt = half ? g_nv1t : g_nv2t;
    float* Out      = half ? g_Trow : g_Srow;

    const int ty = tid & 15;
    const int tx = tid >> 4;
    const int lk = tid >> 3;
    const int lo = (tid & 7) * 16;
    const uint32_t smb = (uint32_t)__cvta_generic_to_shared(sm);

    unsigned long long acc[4][8];
#pragma unroll
    for (int p = 0; p < 4; p++)
#pragma unroll
        for (int c = 0; c < 8; c++) acc[p][c] = 0ull;

    GEMM_ISSUE(0);

    // zero the output (streaming stores) — drains under the mainloop
    {
        const float4 z = make_float4(0.f, 0.f, 0.f, 0.f);
        float4* o4 = (float4*)out;
        const size_t total4 = (size_t)NN * NN / 4;
        for (size_t i = (size_t)blockIdx.x * 256 + tid; i < total4;
             i += (size_t)gridDim.x * 256)
            __stcs(&o4[i], z);
    }

    for (int ch = 0; ch < 8; ch++) {
        if (ch < 7) {
            GEMM_ISSUE(ch + 1);
            asm volatile("cp.async.wait_group 1;");
        } else {
            asm volatile("cp.async.wait_group 0;");
        }
        __syncthreads();

        const float* A = sm + (ch & 1) * ABUF;
        const float* B = A + 4096;
#pragma unroll
        for (int k = 0; k < 32; k++) {
            ulonglong2 a01 = *(const ulonglong2*)&A[k * 128 + ty * 8];
            ulonglong2 a23 = *(const ulonglong2*)&A[k * 128 + ty * 8 + 4];
            float4 bv0 = *(const float4*)&B[k * 128 + tx * 8];
            float4 bv1 = *(const float4*)&B[k * 128 + tx * 8 + 4];
            unsigned long long ap[4] = {a01.x, a01.y, a23.x, a23.y};
            unsigned long long bd[8] = {dup2(bv0.x), dup2(bv0.y), dup2(bv0.z), dup2(bv0.w),
                                        dup2(bv1.x), dup2(bv1.y), dup2(bv1.z), dup2(bv1.w)};
#pragma unroll
            for (int c = 0; c < 8; c++)
#pragma unroll
                for (int p = 0; p < 4; p++)
                    fma2(acc[p][c], ap[p], bd[c]);
        }
        __syncthreads();
    }

    // epilogue: compact stripe buffer, row pitch STRIPE_COLS
#pragma unroll
    for (int p = 0; p < 4; p++) {
        float2 u0 = unpk(acc[p][0]), u1 = unpk(acc[p][1]);
        float2 u2 = unpk(acc[p][2]), u3 = unpk(acc[p][3]);
        float2 u4 = unpk(acc[p][4]), u5 = unpk(acc[p][5]);
        float2 u6 = unpk(acc[p][6]), u7 = unpk(acc[p][7]);
        size_t base = (size_t)(rowBase + ty * 8 + 2 * p) * STRIPE_COLS + colBase + tx * 8;
        *(float4*)&Out[base]               = make_float4(u0.x, u1.x, u2.x, u3.x);
        *(float4*)&Out[base + 4]           = make_float4(u4.x, u5.x, u6.x, u7.x);
        *(float4*)&Out[base + STRIPE_COLS]     = make_float4(u0.y, u1.y, u2.y, u3.y);
        *(float4*)&Out[base + STRIPE_COLS + 4] = make_float4(u4.y, u5.y, u6.y, u7.y);
    }
}

// ---------------------------------------------------------------------------
// Kernel B (warp-per-row, no smem, no syncs): ballot-collect the first 32
// exact-1.0 columns per row from the compact stripe buffers (coalesced,
// L2-warm). Ascending column order -> identical pick semantics to the
// validated staged version. Fallback: generic exact streaming top-32.
// ---------------------------------------------------------------------------
__device__ void generic_row_topk(int r, float* __restrict__ out) {
    const int lane = threadIdx.x & 31;
    unsigned long long key = 0ull, rmin = 0ull;
    for (int cb = 0; cb < NN; cb += 32) {
        int c = cb + lane;
        float sv, tv;
        if (cb + 32 <= STRIPE_COLS) {
            sv = g_Srow[(size_t)r * STRIPE_COLS + c];
            tv = g_Trow[(size_t)r * STRIPE_COLS + c];
        } else {
            sv = s_compute(r, c);
            tv = t_compute(r, c);
        }
        float v = adj_val(__fsub_rn(sv, tv));
        unsigned long long cand =
            ((unsigned long long)__float_as_uint(v) << 32)
            | (unsigned)(0xFFFFFFFFu - (unsigned)c);
        unsigned m = __ballot_sync(FULLM, cand > rmin);
        while (m) {
            int src = __ffs(m) - 1; m &= m - 1;
            unsigned long long ck = __shfl_sync(FULLM, cand, src);
            if (ck > rmin) {
                unsigned bal = __ballot_sync(FULLM, key == rmin);
                if (lane == (__ffs(bal) - 1)) key = ck;
                unsigned long long mm = key;
#pragma unroll
                for (int o = 16; o > 0; o >>= 1) {
                    unsigned long long om = __shfl_xor_sync(FULLM, mm, o);
                    mm = om < mm ? om : mm;
                }
                rmin = mm;
            }
        }
    }
    unsigned vb = (unsigned)(key >> 32);
    if (vb) {
        unsigned col = 0xFFFFFFFFu - (unsigned)(key & 0xFFFFFFFFull);
        out[(size_t)r * NN + col] = __uint_as_float(vb);
    }
}

__global__ __launch_bounds__(256) void topk_kernel(float* __restrict__ out) {
    const int r    = (blockIdx.x * 256 + threadIdx.x) >> 5;   // row = global warp id
    const int lane = threadIdx.x & 31;

    // prefetch the whole stripe row (8 chunk-pairs, coalesced, MLP=16)
    float sv[8], tv[8];
#pragma unroll
    for (int j = 0; j < 8; j++) {
        sv[j] = g_Srow[(size_t)r * STRIPE_COLS + j * 32 + lane];
        tv[j] = g_Trow[(size_t)r * STRIPE_COLS + j * 32 + lane];
    }

    int cnt = 0, mycol = -1;
#pragma unroll
    for (int j = 0; j < 8; j++) {
        if (cnt >= 32) break;                       // warp-uniform
        float v = adj_val(__fsub_rn(sv[j], tv[j]));
        unsigned m = __ballot_sync(FULLM, v == 1.0f);
        int avail = __popc(m);
        int nc = min(32 - cnt, avail);
        int sl = lane - cnt;
        if (sl >= 0 && sl < nc)
            mycol = j * 32 + __fns(m, 0, sl + 1);
        cnt += nc;
    }

    if (cnt >= 32) {
        // output pre-zeroed; every collected value is exactly 1.0f
        if (mycol >= 0)
            out[(size_t)r * NN + mycol] = 1.0f;
    } else {
        // probability-~0 fallback: full exact streaming top-32 for this row
        generic_row_topk(r, out);
    }
}

// ---------------------------------------------------------------------------
// Inputs (metadata order): idx(int64), scale_idx, scale_set, emb1, emb2,
//                          W1, b1, W2, b2.  Output: float32 [8192*8192].
// ---------------------------------------------------------------------------
extern "C" void kernel_launch(void* const* d_in, const int* in_sizes, int n_in,
                              void* d_out, int out_size) {
    const float* emb1 = (const float*)d_in[3];
    const float* emb2 = (const float*)d_in[4];
    const float* W1   = (const float*)d_in[5];
    const float* b1   = (const float*)d_in[6];
    const float* W2   = (const float*)d_in[7];
    const float* b2   = (const float*)d_in[8];
    float* out = (float*)d_out;

    (void)in_sizes; (void)n_in; (void)out_size;

    static const size_t GEMM_SMEM = 2 * ABUF * sizeof(float);            // 64KB
    cudaFuncSetAttribute(nv_gemm_kernel,
                         cudaFuncAttributeMaxDynamicSharedMemorySize, (int)GEMM_SMEM);
    cudaFuncSetAttribute(s_gemm_kernel,
                         cudaFuncAttributeMaxDynamicSharedMemorySize, (int)GEMM_SMEM);

    // 1) exact transposes: embT [k][node], WT [k][col] (no dead blocks)
    transpose_kernel<<<dim3(DIMK / 32, 264, 2), 256>>>(emb1, emb2, W1, W2);

    // 2) nv GEMM (both sets): nvT = tanh(3*(emb @ W^T + b))^T
    nv_gemm_kernel<<<dim3(NN / 128, DIMK / 128, 2), 256, GEMM_SMEM>>>(b1, b2);

    // 3) dual row-stripe GEMM (S and T) + output zeroing under the mainloop
    s_gemm_kernel<<<256, 256, GEMM_SMEM>>>(out);

    // 4) warp-per-row top-32 collect + scatter (no smem, no syncs)
    topk_kernel<<<NN / 8, 256>>>(out);
}

// round 17
// speedup vs baseline: 1.5653x; 1.0735x over previous
#include <cuda_runtime.h>
#include <cstdint>

#define NN   8192
#define DIMK 256
#define FULLM 0xFFFFFFFFu

// XLA EmitTanh f32 clamp constant (validated: rel_err == 0.0)
#define KMAX_TANH 7.99881172180175781f

// Stripe width: per-row saturated count in 256 cols ~ Binom(256,0.41):
// mean 105, sigma 7.9 -> P(<32) ~ 1e-20. Cold path backstops correctness.
#define STRIPE_TILES 2            // 2 tiles x 128 cols = 256
#define STRIPE_COLS  (STRIPE_TILES * 128)

// Scratch (device globals — no allocation allowed)
__device__ float g_e1t[DIMK * NN];             // emb1^T  [k][node]
__device__ float g_e2t[DIMK * NN];             // emb2^T
__device__ float g_w1t[DIMK * DIMK];           // W1^T    [k][col]
__device__ float g_w2t[DIMK * DIMK];           // W2^T
__device__ float g_nv1t[DIMK * NN];            // nv1^T   [k][node]
__device__ float g_nv2t[DIMK * NN];            // nv2^T
__device__ float g_Srow[(size_t)NN * STRIPE_COLS];  // S[r][c], c<256   (8MB)
__device__ float g_Trow[(size_t)NN * STRIPE_COLS];  // T[r][c]=S[c][r]  (8MB)

// ---------------------------------------------------------------------------
// Eigen/XLA rational tanh (fma Horner), clamped at +/-KMAX_TANH.
// ---------------------------------------------------------------------------
__device__ __forceinline__ float tanh_nv(float x) {
    float t = fminf(fmaxf(x, -KMAX_TANH), KMAX_TANH);
    float x2 = __fmul_rn(t, t);
    float p = fmaf(x2, -2.76076847742355e-16f, 2.00018790482477e-13f);
    p = fmaf(x2, p, -8.60467152213735e-11f);
    p = fmaf(x2, p,  5.12229709037114e-08f);
    p = fmaf(x2, p,  1.48572235717979e-05f);
    p = fmaf(x2, p,  6.37261928875436e-04f);
    p = fmaf(x2, p,  4.89352455891786e-03f);
    p = __fmul_rn(t, p);
    float q = fmaf(x2, 1.19825839466702e-06f, 1.18534705686654e-04f);
    q = fmaf(x2, q, 2.26843463243900e-03f);
    q = fmaf(x2, q, 4.89352518554385e-03f);
    float r = __fdiv_rn(p, q);
    return (fabsf(x) < 0.0004f) ? x : r;
}

// relu(tanh(3a)) with the decision boundary explicit (tie class == 1.0f).
__device__ __forceinline__ float adj_val(float a) {
    float x = __fmul_rn(3.0f, a);
    if (x >= KMAX_TANH) return 1.0f;
    if (x <= 0.0f)      return 0.0f;
    float x2 = __fmul_rn(x, x);
    float p = fmaf(x2, -2.76076847742355e-16f, 2.00018790482477e-13f);
    p = fmaf(x2, p, -8.60467152213735e-11f);
    p = fmaf(x2, p,  5.12229709037114e-08f);
    p = fmaf(x2, p,  1.48572235717979e-05f);
    p = fmaf(x2, p,  6.37261928875436e-04f);
    p = fmaf(x2, p,  4.89352455891786e-03f);
    p = __fmul_rn(x, p);
    float q = fmaf(x2, 1.19825839466702e-06f, 1.18534705686654e-04f);
    q = fmaf(x2, q, 2.26843463243900e-03f);
    q = fmaf(x2, q, 4.89352518554385e-03f);
    float r = __fdiv_rn(p, q);
    return (x < 0.0004f) ? x : r;
}

// Packed f32x2 helpers (each lane rounds exactly like a scalar FFMA)
__device__ __forceinline__ unsigned long long dup2(float x) {
    unsigned long long r;
    asm("mov.b64 %0, {%1, %1};" : "=l"(r) : "f"(x));
    return r;
}
__device__ __forceinline__ void fma2(unsigned long long& d,
                                     unsigned long long a,
                                     unsigned long long b) {
    asm("fma.rn.f32x2 %0, %1, %2, %0;" : "+l"(d) : "l"(a), "l"(b));
}
__device__ __forceinline__ float2 unpk(unsigned long long v) {
    float2 f;
    asm("mov.b64 {%0, %1}, %2;" : "=f"(f.x), "=f"(f.y) : "l"(v));
    return f;
}

__device__ __forceinline__ void cpasync16(uint32_t dst, const float* src) {
    asm volatile("cp.async.cg.shared.global [%0], [%1], 16;" :: "r"(dst), "l"(src));
}

// Cold-path recompute: identical ascending-k fmaf chains.
__device__ __forceinline__ float s_compute(int r, int c) {        // S[r][c]
    float acc = 0.0f;
    for (int k = 0; k < DIMK; k++)
        acc = fmaf(g_nv1t[(size_t)k * NN + r], g_nv2t[(size_t)k * NN + c], acc);
    return acc;
}
__device__ __forceinline__ float t_compute(int r, int c) {        // T[r][c]=S[c][r]
    float acc = 0.0f;
    for (int k = 0; k < DIMK; k++)
        acc = fmaf(g_nv2t[(size_t)k * NN + r], g_nv1t[(size_t)k * NN + c], acc);
    return acc;
}

// ---------------------------------------------------------------------------
// Transpose pre-pass (exact copies). Grid (8, 264, 2): y<256 -> emb tile,
// y>=256 -> W tile; z selects set 1/2. No dead blocks.
// ---------------------------------------------------------------------------
__global__ __launch_bounds__(256) void transpose_kernel(const float* __restrict__ e1,
                                                        const float* __restrict__ e2,
                                                        const float* __restrict__ w1,
                                                        const float* __restrict__ w2) {
    __shared__ float tile[32][33];
    const int z = blockIdx.z;
    const int yy = blockIdx.y;
    const float* src;
    float* dst;
    int R, by;
    if (yy < 256) { src = z ? e2 : e1; dst = z ? g_e2t : g_e1t; R = NN;   by = yy * 32; }
    else          { src = z ? w2 : w1; dst = z ? g_w2t : g_w1t; R = DIMK; by = (yy - 256) * 32; }
    const int bx = blockIdx.x * 32;

    const int tx = threadIdx.x & 31, ty = threadIdx.x >> 5;
#pragma unroll
    for (int i = ty; i < 32; i += 8)
        tile[i][tx] = src[(size_t)(by + i) * DIMK + bx + tx];
    __syncthreads();
#pragma unroll
    for (int i = ty; i < 32; i += 8)
        dst[(size_t)(bx + i) * R + by + tx] = tile[tx][i];
}

// ---------------------------------------------------------------------------
// nv GEMM (validated shape): nvT = tanh(3*(emb @ W^T + b))^T.
// 256 threads, 8x8 thread tile, cp.async double buffer, fma2 row pairs.
// Also zeroes the FIRST HALF of the 256MB output under its mainloop
// (this kernel is compute-bound with DRAM headroom).
// ---------------------------------------------------------------------------
#define ABUF 8192   // floats per buffer: A tile 4096 + B tile 4096

#define NV_ISSUE(ch)                                                           \
    do {                                                                       \
        int _buf = (ch) & 1;                                                   \
        const float* _a = &At[(size_t)((ch) * 32 + lk) * NN + rowBase + lo];   \
        const float* _b = &Bt[(size_t)((ch) * 32 + lk) * DIMK + colBase + lo]; \
        uint32_t _da = smb + (uint32_t)(_buf * ABUF + lk * 128 + lo) * 4u;     \
        cpasync16(_da,      _a);     cpasync16(_da + 16, _a + 4);              \
        cpasync16(_da + 32, _a + 8); cpasync16(_da + 48, _a + 12);             \
        uint32_t _db = _da + 4096u * 4u;                                       \
        cpasync16(_db,      _b);     cpasync16(_db + 16, _b + 4);              \
        cpasync16(_db + 32, _b + 8); cpasync16(_db + 48, _b + 12);             \
        asm volatile("cp.async.commit_group;");                                \
    } while (0)

__global__ __launch_bounds__(256, 2) void nv_gemm_kernel(const float* __restrict__ b1,
                                                         const float* __restrict__ b2,
                                                         float* __restrict__ out) {
    extern __shared__ float sm[];
    const int tid = threadIdx.x;
    const int sel = blockIdx.z;
    const float* At   = sel ? g_e2t : g_e1t;
    const float* Bt   = sel ? g_w2t : g_w1t;
    const float* bias = sel ? b2 : b1;
    float* nvT = sel ? g_nv2t : g_nv1t;

    const int rowBase = blockIdx.x * 128;
    const int colBase = blockIdx.y * 128;
    const int ty = tid & 15;
    const int tx = tid >> 4;
    const int lk = tid >> 3;
    const int lo = (tid & 7) * 16;
    const uint32_t smb = (uint32_t)__cvta_generic_to_shared(sm);

    unsigned long long acc[4][8];
#pragma unroll
    for (int p = 0; p < 4; p++)
#pragma unroll
        for (int c = 0; c < 8; c++) acc[p][c] = 0ull;

    NV_ISSUE(0);

    // zero the FIRST HALF of the output — drains under the FMA mainloop
    {
        const float4 z = make_float4(0.f, 0.f, 0.f, 0.f);
        float4* o4 = (float4*)out;
        const size_t half4 = (size_t)NN * NN / 8;          // half the float4s
        const size_t nthr  = (size_t)256 * 64 * 2 * 2;     // grid size * block
        const size_t gid   = ((size_t)((blockIdx.z * gridDim.y + blockIdx.y) * gridDim.x
                                       + blockIdx.x)) * 256 + tid;
        for (size_t i = gid; i < half4; i += nthr)
            __stcs(&o4[i], z);
    }

    for (int ch = 0; ch < 8; ch++) {
        if (ch < 7) {
            NV_ISSUE(ch + 1);
            asm volatile("cp.async.wait_group 1;");
        } else {
            asm volatile("cp.async.wait_group 0;");
        }
        __syncthreads();

        const float* A = sm + (ch & 1) * ABUF;
        const float* B = A + 4096;
#pragma unroll
        for (int k = 0; k < 32; k++) {
            ulonglong2 a01 = *(const ulonglong2*)&A[k * 128 + ty * 8];
            ulonglong2 a23 = *(const ulonglong2*)&A[k * 128 + ty * 8 + 4];
            float4 bv0 = *(const float4*)&B[k * 128 + tx * 8];
            float4 bv1 = *(const float4*)&B[k * 128 + tx * 8 + 4];
            unsigned long long ap[4] = {a01.x, a01.y, a23.x, a23.y};
            unsigned long long bd[8] = {dup2(bv0.x), dup2(bv0.y), dup2(bv0.z), dup2(bv0.w),
                                        dup2(bv1.x), dup2(bv1.y), dup2(bv1.z), dup2(bv1.w)};
#pragma unroll
            for (int c = 0; c < 8; c++)
#pragma unroll
                for (int p = 0; p < 4; p++)
                    fma2(acc[p][c], ap[p], bd[c]);
        }
        __syncthreads();
    }

    // epilogue: y = 3*(acc+b) (unfused add then mul), tanh, store transposed.
#pragma unroll
    for (int c = 0; c < 8; c++) {
        const int col = colBase + tx * 8 + c;
        const float b = bias[col];
        float2 v01 = unpk(acc[0][c]), v23 = unpk(acc[1][c]);
        float2 v45 = unpk(acc[2][c]), v67 = unpk(acc[3][c]);
        float4 o0, o1;
        o0.x = tanh_nv(__fmul_rn(3.0f, __fadd_rn(v01.x, b)));
        o0.y = tanh_nv(__fmul_rn(3.0f, __fadd_rn(v01.y, b)));
        o0.z = tanh_nv(__fmul_rn(3.0f, __fadd_rn(v23.x, b)));
        o0.w = tanh_nv(__fmul_rn(3.0f, __fadd_rn(v23.y, b)));
        o1.x = tanh_nv(__fmul_rn(3.0f, __fadd_rn(v45.x, b)));
        o1.y = tanh_nv(__fmul_rn(3.0f, __fadd_rn(v45.y, b)));
        o1.z = tanh_nv(__fmul_rn(3.0f, __fadd_rn(v67.x, b)));
        o1.w = tanh_nv(__fmul_rn(3.0f, __fadd_rn(v67.y, b)));
        size_t base = (size_t)col * NN + rowBase + ty * 8;
        *(float4*)&nvT[base]     = o0;
        *(float4*)&nvT[base + 4] = o1;
    }
}

// ---------------------------------------------------------------------------
// Kernel A: dual row-stripe GEMM.  256 CTAs:
//   bid <  128:  S[r][c] = sum_k nv1t[k][r]*nv2t[k][c]  -> g_Srow
//   bid >= 128:  T[r][c] = sum_k nv2t[k][r]*nv1t[k][c]  -> g_Trow (== S[c][r]
//                bitwise: mul commutes; same ascending-k chain)
// Zeroes the SECOND HALF of the output under its mainloop.
// ---------------------------------------------------------------------------
#define GEMM_ISSUE(ch)                                                         \
    do {                                                                       \
        int _buf = (ch) & 1;                                                   \
        const float* _a = &At[(size_t)((ch) * 32 + lk) * NN + rowBase + lo];   \
        const float* _b = &Bt[(size_t)((ch) * 32 + lk) * NN + colBase + lo];   \
        uint32_t _da = smb + (uint32_t)(_buf * ABUF + lk * 128 + lo) * 4u;     \
        cpasync16(_da,      _a);     cpasync16(_da + 16, _a + 4);              \
        cpasync16(_da + 32, _a + 8); cpasync16(_da + 48, _a + 12);             \
        uint32_t _db = _da + 4096u * 4u;                                       \
        cpasync16(_db,      _b);     cpasync16(_db + 16, _b + 4);              \
        cpasync16(_db + 32, _b + 8); cpasync16(_db + 48, _b + 12);             \
        asm volatile("cp.async.commit_group;");                                \
    } while (0)

__global__ __launch_bounds__(256, 2) void s_gemm_kernel(float* __restrict__ out) {
    extern __shared__ float sm[];
    const int tid = threadIdx.x;

    const int bid  = blockIdx.x;          // 0..255
    const int half = bid >> 7;            // 0: S, 1: T
    const int b    = bid & 127;
    const int rowBase = (b >> 1) * 128;
    const int colBase = (b & 1) * 128;
    const float* At = half ? g_nv2t : g_nv1t;
    const float* Bt = half ? g_nv1t : g_nv2t;
    float* Out      = half ? g_Trow : g_Srow;

    const int ty = tid & 15;
    const int tx = tid >> 4;
    const int lk = tid >> 3;
    const int lo = (tid & 7) * 16;
    const uint32_t smb = (uint32_t)__cvta_generic_to_shared(sm);

    unsigned long long acc[4][8];
#pragma unroll
    for (int p = 0; p < 4; p++)
#pragma unroll
        for (int c = 0; c < 8; c++) acc[p][c] = 0ull;

    GEMM_ISSUE(0);

    // zero the SECOND HALF of the output — drains under the mainloop
    {
        const float4 z = make_float4(0.f, 0.f, 0.f, 0.f);
        float4* o4 = (float4*)out;
        const size_t half4  = (size_t)NN * NN / 8;
        const size_t total4 = (size_t)NN * NN / 4;
        for (size_t i = half4 + (size_t)blockIdx.x * 256 + tid; i < total4;
             i += (size_t)gridDim.x * 256)
            __stcs(&o4[i], z);
    }

    for (int ch = 0; ch < 8; ch++) {
        if (ch < 7) {
            GEMM_ISSUE(ch + 1);
            asm volatile("cp.async.wait_group 1;");
        } else {
            asm volatile("cp.async.wait_group 0;");
        }
        __syncthreads();

        const float* A = sm + (ch & 1) * ABUF;
        const float* B = A + 4096;
#pragma unroll
        for (int k = 0; k < 32; k++) {
            ulonglong2 a01 = *(const ulonglong2*)&A[k * 128 + ty * 8];
            ulonglong2 a23 = *(const ulonglong2*)&A[k * 128 + ty * 8 + 4];
            float4 bv0 = *(const float4*)&B[k * 128 + tx * 8];
            float4 bv1 = *(const float4*)&B[k * 128 + tx * 8 + 4];
            unsigned long long ap[4] = {a01.x, a01.y, a23.x, a23.y};
            unsigned long long bd[8] = {dup2(bv0.x), dup2(bv0.y), dup2(bv0.z), dup2(bv0.w),
                                        dup2(bv1.x), dup2(bv1.y), dup2(bv1.z), dup2(bv1.w)};
#pragma unroll
            for (int c = 0; c < 8; c++)
#pragma unroll
                for (int p = 0; p < 4; p++)
                    fma2(acc[p][c], ap[p], bd[c]);
        }
        __syncthreads();
    }

    // epilogue: compact stripe buffer, row pitch STRIPE_COLS
#pragma unroll
    for (int p = 0; p < 4; p++) {
        float2 u0 = unpk(acc[p][0]), u1 = unpk(acc[p][1]);
        float2 u2 = unpk(acc[p][2]), u3 = unpk(acc[p][3]);
        float2 u4 = unpk(acc[p][4]), u5 = unpk(acc[p][5]);
        float2 u6 = unpk(acc[p][6]), u7 = unpk(acc[p][7]);
        size_t base = (size_t)(rowBase + ty * 8 + 2 * p) * STRIPE_COLS + colBase + tx * 8;
        *(float4*)&Out[base]               = make_float4(u0.x, u1.x, u2.x, u3.x);
        *(float4*)&Out[base + 4]           = make_float4(u4.x, u5.x, u6.x, u7.x);
        *(float4*)&Out[base + STRIPE_COLS]     = make_float4(u0.y, u1.y, u2.y, u3.y);
        *(float4*)&Out[base + STRIPE_COLS + 4] = make_float4(u4.y, u5.y, u6.y, u7.y);
    }
}

// ---------------------------------------------------------------------------
// Kernel B (warp-per-row, no smem, no syncs): ballot-collect the first 32
// exact-1.0 columns per row from the compact stripe buffers (coalesced,
// L2-warm). Fallback: generic exact streaming top-32 (probability ~0).
// ---------------------------------------------------------------------------
__device__ void generic_row_topk(int r, float* __restrict__ out) {
    const int lane = threadIdx.x & 31;
    unsigned long long key = 0ull, rmin = 0ull;
    for (int cb = 0; cb < NN; cb += 32) {
        int c = cb + lane;
        float sv, tv;
        if (cb + 32 <= STRIPE_COLS) {
            sv = g_Srow[(size_t)r * STRIPE_COLS + c];
            tv = g_Trow[(size_t)r * STRIPE_COLS + c];
        } else {
            sv = s_compute(r, c);
            tv = t_compute(r, c);
        }
        float v = adj_val(__fsub_rn(sv, tv));
        unsigned long long cand =
            ((unsigned long long)__float_as_uint(v) << 32)
            | (unsigned)(0xFFFFFFFFu - (unsigned)c);
        unsigned m = __ballot_sync(FULLM, cand > rmin);
        while (m) {
            int src = __ffs(m) - 1; m &= m - 1;
            unsigned long long ck = __shfl_sync(FULLM, cand, src);
            if (ck > rmin) {
                unsigned bal = __ballot_sync(FULLM, key == rmin);
                if (lane == (__ffs(bal) - 1)) key = ck;
                unsigned long long mm = key;
#pragma unroll
                for (int o = 16; o > 0; o >>= 1) {
                    unsigned long long om = __shfl_xor_sync(FULLM, mm, o);
                    mm = om < mm ? om : mm;
                }
                rmin = mm;
            }
        }
    }
    unsigned vb = (unsigned)(key >> 32);
    if (vb) {
        unsigned col = 0xFFFFFFFFu - (unsigned)(key & 0xFFFFFFFFull);
        out[(size_t)r * NN + col] = __uint_as_float(vb);
    }
}

__global__ __launch_bounds__(256) void topk_kernel(float* __restrict__ out) {
    const int r    = (blockIdx.x * 256 + threadIdx.x) >> 5;   // row = global warp id
    const int lane = threadIdx.x & 31;

    // prefetch the whole stripe row (8 chunk-pairs, coalesced, MLP=16)
    float sv[8], tv[8];
#pragma unroll
    for (int j = 0; j < 8; j++) {
        sv[j] = g_Srow[(size_t)r * STRIPE_COLS + j * 32 + lane];
        tv[j] = g_Trow[(size_t)r * STRIPE_COLS + j * 32 + lane];
    }

    int cnt = 0, mycol = -1;
#pragma unroll
    for (int j = 0; j < 8; j++) {
        if (cnt >= 32) break;                       // warp-uniform
        float v = adj_val(__fsub_rn(sv[j], tv[j]));
        unsigned m = __ballot_sync(FULLM, v == 1.0f);
        int avail = __popc(m);
        int nc = min(32 - cnt, avail);
        int sl = lane - cnt;
        if (sl >= 0 && sl < nc)
            mycol = j * 32 + __fns(m, 0, sl + 1);
        cnt += nc;
    }

    if (cnt >= 32) {
        // output pre-zeroed; every collected value is exactly 1.0f
        if (mycol >= 0)
            out[(size_t)r * NN + mycol] = 1.0f;
    } else {
        // probability-~0 fallback: full exact streaming top-32 for this row
        generic_row_topk(r, out);
    }
}

// ---------------------------------------------------------------------------
// Inputs (metadata order): idx(int64), scale_idx, scale_set, emb1, emb2,
//                          W1, b1, W2, b2.  Output: float32 [8192*8192].
// ---------------------------------------------------------------------------
extern "C" void kernel_launch(void* const* d_in, const int* in_sizes, int n_in,
                              void* d_out, int out_size) {
    const float* emb1 = (const float*)d_in[3];
    const float* emb2 = (const float*)d_in[4];
    const float* W1   = (const float*)d_in[5];
    const float* b1   = (const float*)d_in[6];
    const float* W2   = (const float*)d_in[7];
    const float* b2   = (const float*)d_in[8];
    float* out = (float*)d_out;

    (void)in_sizes; (void)n_in; (void)out_size;

    static const size_t GEMM_SMEM = 2 * ABUF * sizeof(float);            // 64KB
    cudaFuncSetAttribute(nv_gemm_kernel,
                         cudaFuncAttributeMaxDynamicSharedMemorySize, (int)GEMM_SMEM);
    cudaFuncSetAttribute(s_gemm_kernel,
                         cudaFuncAttributeMaxDynamicSharedMemorySize, (int)GEMM_SMEM);

    // 1) exact transposes: embT [k][node], WT [k][col] (no dead blocks)
    transpose_kernel<<<dim3(DIMK / 32, 264, 2), 256>>>(emb1, emb2, W1, W2);

    // 2) nv GEMM (both sets) + zero first half of output under the mainloop
    nv_gemm_kernel<<<dim3(NN / 128, DIMK / 128, 2), 256, GEMM_SMEM>>>(b1, b2, out);

    // 3) dual row-stripe GEMM (S and T) + zero second half of output
    s_gemm_kernel<<<256, 256, GEMM_SMEM>>>(out);

    // 4) warp-per-row top-32 collect + scatter (no smem, no syncs)
    topk_kernel<<<NN / 8, 256>>>(out);
}